// round 2
// baseline (speedup 1.0000x reference)
#include <cuda_runtime.h>
#include <cuda_bf16.h>
#include <cstdint>
#include <cstddef>

#define BB    8
#define CIN   768
#define LSEQ  4096
#define CH    96
#define COUTC 768

// ---- device-global scratch (no allocations allowed) ----
__device__ float g_Q[BB * LSEQ * CH];
__device__ float g_K[BB * LSEQ * CH];
__device__ float g_V[BB * LSEQ * CH];
__device__ float g_O[BB * LSEQ * CH];

// ============================================================================
// Kernel 1: QKV projection.  Out[b,l,o] = sum_c W[o,c] * x[b,c,l]
// Block: 64 l x 96 o. 256 threads: (tl: 4 l) x (tn: 6 o). K chunks of 32.
// ============================================================================
__global__ __launch_bounds__(256) void proj_kernel(
    const float* __restrict__ x,
    const float* __restrict__ Wq,
    const float* __restrict__ Wk,
    const float* __restrict__ Wv)
{
    __shared__ float xs[32][64];   // [c][l]
    __shared__ float ws[32][CH];   // [c][o] transposed tile

    const int l0 = blockIdx.x * 64;
    const int b  = blockIdx.z;
    const float* W;
    float* Out;
    if (blockIdx.y == 0)      { W = Wq; Out = g_Q; }
    else if (blockIdx.y == 1) { W = Wk; Out = g_K; }
    else                      { W = Wv; Out = g_V; }

    const int tid = threadIdx.x;
    const int tl  = tid >> 4;   // 0..15 -> 4 l rows each
    const int tn  = tid & 15;   // 0..15 -> 6 outputs each

    float acc[4][6];
#pragma unroll
    for (int i = 0; i < 4; ++i)
#pragma unroll
        for (int j = 0; j < 6; ++j) acc[i][j] = 0.f;

    const float* xb = x + (size_t)b * CIN * LSEQ + l0;

    for (int c0 = 0; c0 < CIN; c0 += 32) {
        __syncthreads();
        // x tile: 32c x 64l = 512 float4, coalesced along l
        {
            int i = tid;
#pragma unroll
            for (int it = 0; it < 2; ++it, i += 256) {
                int cc = i >> 4, l4 = i & 15;
                float4 v = *(const float4*)(xb + (size_t)(c0 + cc) * LSEQ + l4 * 4);
                *(float4*)&xs[cc][l4 * 4] = v;
            }
        }
        // W tile transposed into ws[c][o]: 96 o x 8 float4 = 768 units
        {
            int i = tid;
#pragma unroll
            for (int it = 0; it < 3; ++it, i += 256) {
                int o = i % 96, c4 = i / 96;
                float4 v = *(const float4*)(W + o * CIN + c0 + c4 * 4);
                ws[c4 * 4 + 0][o] = v.x;
                ws[c4 * 4 + 1][o] = v.y;
                ws[c4 * 4 + 2][o] = v.z;
                ws[c4 * 4 + 3][o] = v.w;
            }
        }
        __syncthreads();

#pragma unroll 4
        for (int cc = 0; cc < 32; ++cc) {
            float av[4];
            av[0] = xs[cc][tl * 4 + 0];
            av[1] = xs[cc][tl * 4 + 1];
            av[2] = xs[cc][tl * 4 + 2];
            av[3] = xs[cc][tl * 4 + 3];
            float2 w0 = *(const float2*)&ws[cc][tn * 6];
            float2 w1 = *(const float2*)&ws[cc][tn * 6 + 2];
            float2 w2 = *(const float2*)&ws[cc][tn * 6 + 4];
            float wv[6] = {w0.x, w0.y, w1.x, w1.y, w2.x, w2.y};
#pragma unroll
            for (int i = 0; i < 4; ++i)
#pragma unroll
                for (int j = 0; j < 6; ++j) acc[i][j] += av[i] * wv[j];
        }
    }

#pragma unroll
    for (int i = 0; i < 4; ++i) {
        float* dst = Out + ((size_t)b * LSEQ + l0 + tl * 4 + i) * CH + tn * 6;
#pragma unroll
        for (int j = 0; j < 6; ++j) dst[j] = acc[i][j];
    }
}

// ============================================================================
// Kernel 2: fp32 flash attention, online softmax.
// Block: 64 queries. 256 threads. Score phase: (qg: 4q) x (kg: 4k).
// PV phase: (qg: 4q) x (kg as cg: 6 channels).
// K stored transposed [c][k] in smem for bank-clean LDS.128 over k.
// ============================================================================
struct AttnSm {
    float Qs[64][CH];    // [q][c]
    float Kt[CH][64];    // [c][k]  (transposed)
    float Vs[64][CH];    // [k][c]
    float Ps[64][68];    // probs, padded
};

__global__ __launch_bounds__(256, 2) void attn_kernel() {
    extern __shared__ char raw[];
    AttnSm& sm = *reinterpret_cast<AttnSm*>(raw);

    const int b   = blockIdx.y;
    const int l0  = blockIdx.x * 64;
    const int tid = threadIdx.x;
    const int qg  = tid >> 4;   // 0..15 -> 4 query rows
    const int kg  = tid & 15;   // 0..15 -> 4 keys (score) / 6 channels (PV)

    const float* Qg = g_Q + ((size_t)b * LSEQ + l0) * CH;
    const float* Kb = g_K + (size_t)b * LSEQ * CH;
    const float* Vb = g_V + (size_t)b * LSEQ * CH;

    // load Q tile once: 1536 float4
    {
        int i = tid;
#pragma unroll
        for (int it = 0; it < 6; ++it, i += 256) {
            int q = i / 24, c4 = i % 24;
            float4 v = *(const float4*)(Qg + q * CH + c4 * 4);
            *(float4*)&sm.Qs[q][c4 * 4] = v;
        }
    }

    float m[4], l[4], acc[4][6];
#pragma unroll
    for (int i = 0; i < 4; ++i) {
        m[i] = -1e30f; l[i] = 0.f;
#pragma unroll
        for (int j = 0; j < 6; ++j) acc[i][j] = 0.f;
    }

    for (int kt = 0; kt < LSEQ / 64; ++kt) {
        const int k0 = kt * 64;
        __syncthreads();   // previous PV finished with Vs/Ps

        // K tile transposed: k contiguous in lanes -> conflict-free STS
        {
            int i = tid;
#pragma unroll
            for (int it = 0; it < 6; ++it, i += 256) {
                int k = i & 63, c4 = i >> 6;
                float4 v = *(const float4*)(Kb + (size_t)(k0 + k) * CH + c4 * 4);
                sm.Kt[c4 * 4 + 0][k] = v.x;
                sm.Kt[c4 * 4 + 1][k] = v.y;
                sm.Kt[c4 * 4 + 2][k] = v.z;
                sm.Kt[c4 * 4 + 3][k] = v.w;
            }
        }
        // V tile natural layout, coalesced
        {
            int i = tid;
#pragma unroll
            for (int it = 0; it < 6; ++it, i += 256) {
                int k = i / 24, c4 = i % 24;
                float4 v = *(const float4*)(Vb + (size_t)(k0 + k) * CH + c4 * 4);
                *(float4*)&sm.Vs[k][c4 * 4] = v;
            }
        }
        __syncthreads();

        // ---- scores: s[4q][4k] over 96 channels ----
        float s[4][4];
#pragma unroll
        for (int i = 0; i < 4; ++i)
#pragma unroll
            for (int j = 0; j < 4; ++j) s[i][j] = 0.f;

#pragma unroll 2
        for (int c4 = 0; c4 < 24; ++c4) {
            float kv[4][4];
#pragma unroll
            for (int cc = 0; cc < 4; ++cc) {
                float4 v = *(const float4*)&sm.Kt[c4 * 4 + cc][kg * 4];
                kv[cc][0] = v.x; kv[cc][1] = v.y; kv[cc][2] = v.z; kv[cc][3] = v.w;
            }
#pragma unroll
            for (int i = 0; i < 4; ++i) {
                float4 qv = *(const float4*)&sm.Qs[qg * 4 + i][c4 * 4];
#pragma unroll
                for (int j = 0; j < 4; ++j) {
                    s[i][j] += qv.x * kv[0][j];
                    s[i][j] += qv.y * kv[1][j];
                    s[i][j] += qv.z * kv[2][j];
                    s[i][j] += qv.w * kv[3][j];
                }
            }
        }

        // ---- online softmax (16-lane reductions across kg) ----
#pragma unroll
        for (int i = 0; i < 4; ++i) {
            float mx = fmaxf(fmaxf(s[i][0], s[i][1]), fmaxf(s[i][2], s[i][3]));
            mx = fmaxf(mx, __shfl_xor_sync(0xffffffffu, mx, 1));
            mx = fmaxf(mx, __shfl_xor_sync(0xffffffffu, mx, 2));
            mx = fmaxf(mx, __shfl_xor_sync(0xffffffffu, mx, 4));
            mx = fmaxf(mx, __shfl_xor_sync(0xffffffffu, mx, 8));
            float mn = fmaxf(m[i], mx);
            float sc = __expf(m[i] - mn);
            float p0 = __expf(s[i][0] - mn);
            float p1 = __expf(s[i][1] - mn);
            float p2 = __expf(s[i][2] - mn);
            float p3 = __expf(s[i][3] - mn);
            float ps = p0 + p1 + p2 + p3;
            ps += __shfl_xor_sync(0xffffffffu, ps, 1);
            ps += __shfl_xor_sync(0xffffffffu, ps, 2);
            ps += __shfl_xor_sync(0xffffffffu, ps, 4);
            ps += __shfl_xor_sync(0xffffffffu, ps, 8);
            l[i] = l[i] * sc + ps;
            m[i] = mn;
#pragma unroll
            for (int j = 0; j < 6; ++j) acc[i][j] *= sc;
            *(float4*)&sm.Ps[qg * 4 + i][kg * 4] = make_float4(p0, p1, p2, p3);
        }
        __syncthreads();

        // ---- PV: acc[q][c] += P[q][k] * V[k][c] ----
#pragma unroll 2
        for (int k = 0; k < 64; ++k) {
            float2 v0 = *(const float2*)&sm.Vs[k][kg * 6];
            float2 v1 = *(const float2*)&sm.Vs[k][kg * 6 + 2];
            float2 v2 = *(const float2*)&sm.Vs[k][kg * 6 + 4];
#pragma unroll
            for (int i = 0; i < 4; ++i) {
                float p = sm.Ps[qg * 4 + i][k];
                acc[i][0] += p * v0.x;
                acc[i][1] += p * v0.y;
                acc[i][2] += p * v1.x;
                acc[i][3] += p * v1.y;
                acc[i][4] += p * v2.x;
                acc[i][5] += p * v2.y;
            }
        }
    }

    // write O[b,l,c]
    float* Og = g_O + ((size_t)b * LSEQ + l0) * CH;
#pragma unroll
    for (int i = 0; i < 4; ++i) {
        float inv = 1.f / l[i];
        float* dst = Og + (qg * 4 + i) * CH + kg * 6;
#pragma unroll
        for (int j = 0; j < 6; ++j) dst[j] = acc[i][j] * inv;
    }
}

// ============================================================================
// Kernel 3: y[b,o,l] = gamma * sum_c Wlast[o,c]*O[b,l,c] + x[b,o,l]
// Block: 64 l x 96 o. 256 threads: (og: 6 o) x (lg: 4 l). float4 writes.
// ============================================================================
__global__ __launch_bounds__(256, 2) void out_kernel(
    const float* __restrict__ x,
    const float* __restrict__ Wlast,
    const float* __restrict__ gammap,
    float* __restrict__ out)
{
    extern __shared__ char raw[];
    float (*Os)[97]  = (float(*)[97])raw;                    // [64][97]
    float (*Wls)[96] = (float(*)[96])(raw + 64 * 97 * 4);    // [c][o]

    const int l0  = blockIdx.x * 64;
    const int o0  = blockIdx.y * 96;
    const int b   = blockIdx.z;
    const int tid = threadIdx.x;
    const int og  = tid >> 4;   // 6 outputs each
    const int lg  = tid & 15;   // 4 l each
    const float gamma = gammap[0];

    // O tile: coalesced
    {
        int i = tid;
#pragma unroll
        for (int it = 0; it < 6; ++it, i += 256) {
            int q = i / 24, c4 = i % 24;
            float4 v = *(const float4*)(g_O + ((size_t)b * LSEQ + l0 + q) * CH + c4 * 4);
            Os[q][c4 * 4 + 0] = v.x;
            Os[q][c4 * 4 + 1] = v.y;
            Os[q][c4 * 4 + 2] = v.z;
            Os[q][c4 * 4 + 3] = v.w;
        }
    }
    // W tile transposed into Wls[c][o]: 96 o x 24 float4 = 2304 units
    {
        int i = tid;
#pragma unroll
        for (int it = 0; it < 9; ++it, i += 256) {
            int o = i % 96, c4 = i / 96;
            float4 v = *(const float4*)(Wlast + (size_t)(o0 + o) * CH + c4 * 4);
            Wls[c4 * 4 + 0][o] = v.x;
            Wls[c4 * 4 + 1][o] = v.y;
            Wls[c4 * 4 + 2][o] = v.z;
            Wls[c4 * 4 + 3][o] = v.w;
        }
    }
    __syncthreads();

    float acc[6][4];
#pragma unroll
    for (int j = 0; j < 6; ++j)
#pragma unroll
        for (int i = 0; i < 4; ++i) acc[j][i] = 0.f;

#pragma unroll 4
    for (int c = 0; c < CH; ++c) {
        float av[4];
        av[0] = Os[lg * 4 + 0][c];
        av[1] = Os[lg * 4 + 1][c];
        av[2] = Os[lg * 4 + 2][c];
        av[3] = Os[lg * 4 + 3][c];
        float2 w0 = *(const float2*)&Wls[c][og * 6];
        float2 w1 = *(const float2*)&Wls[c][og * 6 + 2];
        float2 w2 = *(const float2*)&Wls[c][og * 6 + 4];
        float wv[6] = {w0.x, w0.y, w1.x, w1.y, w2.x, w2.y};
#pragma unroll
        for (int j = 0; j < 6; ++j)
#pragma unroll
            for (int i = 0; i < 4; ++i) acc[j][i] += wv[j] * av[i];
    }

#pragma unroll
    for (int j = 0; j < 6; ++j) {
        size_t base = (size_t)b * COUTC * LSEQ + (size_t)(o0 + og * 6 + j) * LSEQ + l0 + lg * 4;
        float4 xr = *(const float4*)(x + base);
        float4 yv = make_float4(gamma * acc[j][0] + xr.x,
                                gamma * acc[j][1] + xr.y,
                                gamma * acc[j][2] + xr.z,
                                gamma * acc[j][3] + xr.w);
        *(float4*)(out + base) = yv;
    }
}

// ============================================================================
extern "C" void kernel_launch(void* const* d_in, const int* in_sizes, int n_in,
                              void* d_out, int out_size) {
    const float* x     = (const float*)d_in[0];
    const float* Wq    = (const float*)d_in[1];
    const float* Wk    = (const float*)d_in[2];
    const float* Wv    = (const float*)d_in[3];
    const float* Wl    = (const float*)d_in[4];
    const float* gamma = (const float*)d_in[5];
    float* out = (float*)d_out;

    // idempotent, capture-safe host-side attribute sets (no allocation)
    cudaFuncSetAttribute(attn_kernel, cudaFuncAttributeMaxDynamicSharedMemorySize,
                         (int)sizeof(AttnSm));
    cudaFuncSetAttribute(out_kernel, cudaFuncAttributeMaxDynamicSharedMemorySize,
                         64 * 97 * 4 + 96 * 96 * 4);

    proj_kernel<<<dim3(64, 3, 8), 256>>>(x, Wq, Wk, Wv);
    attn_kernel<<<dim3(64, 8), 256, sizeof(AttnSm)>>>();
    out_kernel<<<dim3(64, 8, 8), 256, 64 * 97 * 4 + 96 * 96 * 4>>>(x, Wl, gamma, out);
}

// round 4
// speedup vs baseline: 1.7191x; 1.7191x over previous
#include <cuda_runtime.h>
#include <cuda_bf16.h>
#include <cstdint>
#include <cstddef>

#define BB    8
#define CIN   768
#define LSEQ  4096
#define CH    96
#define COUTC 768

// ---- device-global scratch (no allocations allowed) ----
__device__ float g_Q[BB * LSEQ * CH];
__device__ float g_K[BB * LSEQ * CH];
__device__ float g_V[BB * LSEQ * CH];
__device__ float g_O[BB * LSEQ * CH];
__device__ float g_S[(size_t)BB * LSEQ * LSEQ];   // 512 MB score scratch

// ============================================================================
// PTX helpers: ldmatrix + mma.sync (baseline PTX, valid on plain sm_103)
// ============================================================================
__device__ __forceinline__ uint32_t s2u(const void* p) {
    return (uint32_t)__cvta_generic_to_shared(p);
}
__device__ __forceinline__ void ldsm4(uint32_t r[4], uint32_t a) {
    asm volatile("ldmatrix.sync.aligned.m8n8.x4.shared.b16 {%0,%1,%2,%3}, [%4];"
                 : "=r"(r[0]), "=r"(r[1]), "=r"(r[2]), "=r"(r[3]) : "r"(a));
}
__device__ __forceinline__ void ldsm2(uint32_t r[2], uint32_t a) {
    asm volatile("ldmatrix.sync.aligned.m8n8.x2.shared.b16 {%0,%1}, [%2];"
                 : "=r"(r[0]), "=r"(r[1]) : "r"(a));
}
__device__ __forceinline__ void ldsm2t(uint32_t r[2], uint32_t a) {
    asm volatile("ldmatrix.sync.aligned.m8n8.x2.trans.shared.b16 {%0,%1}, [%2];"
                 : "=r"(r[0]), "=r"(r[1]) : "r"(a));
}
__device__ __forceinline__ void mma_bf16(float d[4], const uint32_t a[4], const uint32_t b[2]) {
    asm volatile("mma.sync.aligned.m16n8k16.row.col.f32.bf16.bf16.f32 "
                 "{%0,%1,%2,%3}, {%4,%5,%6,%7}, {%8,%9}, {%0,%1,%2,%3};"
                 : "+f"(d[0]), "+f"(d[1]), "+f"(d[2]), "+f"(d[3])
                 : "r"(a[0]), "r"(a[1]), "r"(a[2]), "r"(a[3]), "r"(b[0]), "r"(b[1]));
}
// split fp32x4 -> bf16 hi/lo, packed 8B stores (eoff must be multiple of 4)
__device__ __forceinline__ void split4(__nv_bfloat16* hiB, __nv_bfloat16* loB,
                                       int eoff, float4 v) {
    float f[4] = {v.x, v.y, v.z, v.w};
    unsigned short h[4], l[4];
#pragma unroll
    for (int i = 0; i < 4; ++i) {
        __nv_bfloat16 hb = __float2bfloat16(f[i]);
        float r = f[i] - __bfloat162float(hb);
        h[i] = __bfloat16_as_ushort(hb);
        l[i] = __bfloat16_as_ushort(__float2bfloat16(r));
    }
    *(uint2*)(hiB + eoff) = make_uint2((uint32_t)h[0] | ((uint32_t)h[1] << 16),
                                       (uint32_t)h[2] | ((uint32_t)h[3] << 16));
    *(uint2*)(loB + eoff) = make_uint2((uint32_t)l[0] | ((uint32_t)l[1] << 16),
                                       (uint32_t)l[2] | ((uint32_t)l[3] << 16));
}
// FFMA-only exp (x <= 0); avoids MUFU throughput floor
__device__ __forceinline__ float fexp(float x) {
    float y = x * 1.4426950408889634f;
    y = fmaxf(y, -126.0f);
    float t = y + 12582912.0f;
    float f = y - (t - 12582912.0f);
    float p =            1.3333558146e-3f;
    p = fmaf(p, f, 9.6181291076e-3f);
    p = fmaf(p, f, 5.5504108664e-2f);
    p = fmaf(p, f, 2.4022650696e-1f);
    p = fmaf(p, f, 6.9314718056e-1f);
    p = fmaf(p, f, 1.0f);
    int e = (__float_as_int(t) - 0x4b400000 + 127) << 23;
    return p * __int_as_float(e);
}

// ============================================================================
// Kernel 1: QKV projection (unchanged; fp32 SIMT)
// ============================================================================
__global__ __launch_bounds__(256) void proj_kernel(
    const float* __restrict__ x,
    const float* __restrict__ Wq,
    const float* __restrict__ Wk,
    const float* __restrict__ Wv)
{
    __shared__ float xs[32][64];
    __shared__ float ws[32][CH];

    const int l0 = blockIdx.x * 64;
    const int b  = blockIdx.z;
    const float* W;
    float* Out;
    if (blockIdx.y == 0)      { W = Wq; Out = g_Q; }
    else if (blockIdx.y == 1) { W = Wk; Out = g_K; }
    else                      { W = Wv; Out = g_V; }

    const int tid = threadIdx.x;
    const int tl  = tid >> 4;
    const int tn  = tid & 15;

    float acc[4][6];
#pragma unroll
    for (int i = 0; i < 4; ++i)
#pragma unroll
        for (int j = 0; j < 6; ++j) acc[i][j] = 0.f;

    const float* xb = x + (size_t)b * CIN * LSEQ + l0;

    for (int c0 = 0; c0 < CIN; c0 += 32) {
        __syncthreads();
        {
            int i = tid;
#pragma unroll
            for (int it = 0; it < 2; ++it, i += 256) {
                int cc = i >> 4, l4 = i & 15;
                float4 v = *(const float4*)(xb + (size_t)(c0 + cc) * LSEQ + l4 * 4);
                *(float4*)&xs[cc][l4 * 4] = v;
            }
        }
        {
            int i = tid;
#pragma unroll
            for (int it = 0; it < 3; ++it, i += 256) {
                int o = i % 96, c4 = i / 96;
                float4 v = *(const float4*)(W + o * CIN + c0 + c4 * 4);
                ws[c4 * 4 + 0][o] = v.x;
                ws[c4 * 4 + 1][o] = v.y;
                ws[c4 * 4 + 2][o] = v.z;
                ws[c4 * 4 + 3][o] = v.w;
            }
        }
        __syncthreads();

#pragma unroll 4
        for (int cc = 0; cc < 32; ++cc) {
            float av[4];
            av[0] = xs[cc][tl * 4 + 0];
            av[1] = xs[cc][tl * 4 + 1];
            av[2] = xs[cc][tl * 4 + 2];
            av[3] = xs[cc][tl * 4 + 3];
            float2 w0 = *(const float2*)&ws[cc][tn * 6];
            float2 w1 = *(const float2*)&ws[cc][tn * 6 + 2];
            float2 w2 = *(const float2*)&ws[cc][tn * 6 + 4];
            float wv[6] = {w0.x, w0.y, w1.x, w1.y, w2.x, w2.y};
#pragma unroll
            for (int i = 0; i < 4; ++i)
#pragma unroll
                for (int j = 0; j < 6; ++j) acc[i][j] += av[i] * wv[j];
        }
    }

#pragma unroll
    for (int i = 0; i < 4; ++i) {
        float* dst = Out + ((size_t)b * LSEQ + l0 + tl * 4 + i) * CH + tn * 6;
#pragma unroll
        for (int j = 0; j < 6; ++j) dst[j] = acc[i][j];
    }
}

// ============================================================================
// Kernel 2: S = Q K^T via mma.sync bf16 split-3.  CTA 128q x 128k, K=96.
// 8 warps = 2m x 4n, warp tile 64x32. smem pitch 104 bf16 (conflict-free ldsm).
// ============================================================================
#define QP 104                       // Q/K smem pitch (bf16 elements)
#define SC_SMEM (4 * 128 * QP * 2)   // Qh,Ql,Kh,Kl = 106496 B

__global__ __launch_bounds__(256, 2) void score_kernel() {
    extern __shared__ char smraw[];
    __nv_bfloat16* Qh = (__nv_bfloat16*)smraw;
    __nv_bfloat16* Ql = Qh + 128 * QP;
    __nv_bfloat16* Kh = Ql + 128 * QP;
    __nv_bfloat16* Kl = Kh + 128 * QP;

    const int tid = threadIdx.x, wid = tid >> 5, lane = tid & 31;
    const int b = blockIdx.y, q0 = blockIdx.x * 128;
    const int wm = wid & 1, wn = wid >> 1;

    // load + split Q tile once (persistent across k-tiles)
    {
        const float* Qg = g_Q + ((size_t)b * LSEQ + q0) * CH;
#pragma unroll
        for (int j = 0; j < 12; ++j) {
            int idx = tid + j * 256;
            int r = idx / 24, c4 = idx % 24;
            float4 v = *(const float4*)(Qg + r * CH + c4 * 4);
            split4(Qh, Ql, r * QP + c4 * 4, v);
        }
    }

    const uint32_t QhS = s2u(Qh), QlS = s2u(Ql), KhS = s2u(Kh), KlS = s2u(Kl);
    const uint32_t aoff = ((wm * 64 + (lane & 15)) * QP + ((lane >> 4) << 3)) * 2;
    const uint32_t bofs = ((wn * 32 + (lane & 7)) * QP + (((lane >> 3) & 1) << 3)) * 2;
    const int gr = lane >> 2, c2 = (lane & 3) * 2;

    for (int kt = 0; kt < 32; ++kt) {
        const int k0 = kt * 128;
        __syncthreads();
        {
            const float* Kg = g_K + ((size_t)b * LSEQ + k0) * CH;
#pragma unroll
            for (int j = 0; j < 12; ++j) {
                int idx = tid + j * 256;
                int r = idx / 24, c4 = idx % 24;
                float4 v = *(const float4*)(Kg + r * CH + c4 * 4);
                split4(Kh, Kl, r * QP + c4 * 4, v);
            }
        }
        __syncthreads();

        float D[4][4][4];
#pragma unroll
        for (int mf = 0; mf < 4; ++mf)
#pragma unroll
            for (int nf = 0; nf < 4; ++nf)
#pragma unroll
                for (int e = 0; e < 4; ++e) D[mf][nf][e] = 0.f;

#pragma unroll
        for (int ks = 0; ks < 6; ++ks) {
            const uint32_t kc = ks * 32;   // 16 bf16 = 32 bytes
            uint32_t A[4][4], L[4][4], Bf[4][2];
#pragma unroll
            for (int mf = 0; mf < 4; ++mf) ldsm4(A[mf], QhS + aoff + mf * 16 * (QP * 2) + kc);
#pragma unroll
            for (int nf = 0; nf < 4; ++nf) ldsm2(Bf[nf], KhS + bofs + nf * 8 * (QP * 2) + kc);
#pragma unroll
            for (int mf = 0; mf < 4; ++mf)
#pragma unroll
                for (int nf = 0; nf < 4; ++nf) mma_bf16(D[mf][nf], A[mf], Bf[nf]);
#pragma unroll
            for (int mf = 0; mf < 4; ++mf) ldsm4(L[mf], QlS + aoff + mf * 16 * (QP * 2) + kc);
#pragma unroll
            for (int mf = 0; mf < 4; ++mf)
#pragma unroll
                for (int nf = 0; nf < 4; ++nf) mma_bf16(D[mf][nf], L[mf], Bf[nf]);
#pragma unroll
            for (int nf = 0; nf < 4; ++nf) ldsm2(Bf[nf], KlS + bofs + nf * 8 * (QP * 2) + kc);
#pragma unroll
            for (int mf = 0; mf < 4; ++mf)
#pragma unroll
                for (int nf = 0; nf < 4; ++nf) mma_bf16(D[mf][nf], A[mf], Bf[nf]);
        }

        // epilogue: direct float2 STG (quad-contiguous 32B segments)
        float* Sout = g_S + ((size_t)b * LSEQ + q0) * LSEQ + k0;
#pragma unroll
        for (int mf = 0; mf < 4; ++mf) {
            int row = wm * 64 + mf * 16 + gr;
#pragma unroll
            for (int nf = 0; nf < 4; ++nf) {
                int col = wn * 32 + nf * 8 + c2;
                *(float2*)(Sout + (size_t)row * LSEQ + col) =
                    make_float2(D[mf][nf][0], D[mf][nf][1]);
                *(float2*)(Sout + (size_t)(row + 8) * LSEQ + col) =
                    make_float2(D[mf][nf][2], D[mf][nf][3]);
            }
        }
    }
}

// ============================================================================
// Kernel 3: in-place row softmax over g_S (FFMA-only exp)
// ============================================================================
__global__ __launch_bounds__(128) void softmax_kernel() {
    const size_t row = blockIdx.x;
    float* S = g_S + row * LSEQ;
    const int tid = threadIdx.x, wid = tid >> 5;

    float v[32];
    float mx = -1e30f;
#pragma unroll
    for (int j = 0; j < 8; ++j) {
        float4 t = *(const float4*)(S + (size_t)(tid + j * 128) * 4);
        v[j * 4 + 0] = t.x; v[j * 4 + 1] = t.y;
        v[j * 4 + 2] = t.z; v[j * 4 + 3] = t.w;
        mx = fmaxf(mx, fmaxf(fmaxf(t.x, t.y), fmaxf(t.z, t.w)));
    }
#pragma unroll
    for (int o = 16; o; o >>= 1) mx = fmaxf(mx, __shfl_xor_sync(0xffffffffu, mx, o));
    __shared__ float redm[4], reds[4];
    if ((tid & 31) == 0) redm[wid] = mx;
    __syncthreads();
    mx = fmaxf(fmaxf(redm[0], redm[1]), fmaxf(redm[2], redm[3]));

    float s = 0.f;
#pragma unroll
    for (int j = 0; j < 32; ++j) { v[j] = fexp(v[j] - mx); s += v[j]; }
#pragma unroll
    for (int o = 16; o; o >>= 1) s += __shfl_xor_sync(0xffffffffu, s, o);
    if ((tid & 31) == 0) reds[wid] = s;
    __syncthreads();
    float inv = 1.f / (reds[0] + reds[1] + reds[2] + reds[3]);

#pragma unroll
    for (int j = 0; j < 8; ++j)
        *(float4*)(S + (size_t)(tid + j * 128) * 4) =
            make_float4(v[j * 4 + 0] * inv, v[j * 4 + 1] * inv,
                        v[j * 4 + 2] * inv, v[j * 4 + 3] * inv);
}

// ============================================================================
// Kernel 4: O = P V via mma.sync bf16 split-3.  CTA 128q x 96c, K=4096
// in 64-wide chunks; accumulators persist in registers.
// 8 warps = 4m x 2n, warp tile 32x48. V consumed via ldmatrix.trans.
// ============================================================================
#define PP 72                         // P smem pitch (bf16)
#define VP 104                        // V smem pitch (bf16)
#define PV_SMEM (2 * 128 * PP * 2 + 2 * 64 * VP * 2)   // 63488 B

__global__ __launch_bounds__(256, 2) void pv_kernel() {
    extern __shared__ char smraw[];
    __nv_bfloat16* Ph = (__nv_bfloat16*)smraw;
    __nv_bfloat16* Pl = Ph + 128 * PP;
    __nv_bfloat16* Vh = Pl + 128 * PP;
    __nv_bfloat16* Vl = Vh + 64 * VP;

    const int tid = threadIdx.x, wid = tid >> 5, lane = tid & 31;
    const int b = blockIdx.y, q0 = blockIdx.x * 128;
    const int wm = wid >> 1, wn = wid & 1;

    const uint32_t PhS = s2u(Ph), PlS = s2u(Pl), VhS = s2u(Vh), VlS = s2u(Vl);
    const uint32_t aoff = ((wm * 32 + (lane & 15)) * PP + ((lane >> 4) << 3)) * 2;
    const uint32_t brow = (lane & 15) * (VP * 2);
    const uint32_t bcol = (wn * 48) * 2;
    const int gr = lane >> 2, c2 = (lane & 3) * 2;

    float D[2][6][4];
#pragma unroll
    for (int mf = 0; mf < 2; ++mf)
#pragma unroll
        for (int nf = 0; nf < 6; ++nf)
#pragma unroll
            for (int e = 0; e < 4; ++e) D[mf][nf][e] = 0.f;

    for (int ct = 0; ct < 64; ++ct) {
        const int k0 = ct * 64;
        __syncthreads();
        // P chunk [128 q][64 k] fp32 -> split
        {
            const float* Pg = g_S + ((size_t)b * LSEQ + q0) * LSEQ + k0;
#pragma unroll
            for (int j = 0; j < 8; ++j) {
                int idx = tid + j * 256;
                int q = idx >> 4, k4 = idx & 15;
                float4 v = *(const float4*)(Pg + (size_t)q * LSEQ + k4 * 4);
                split4(Ph, Pl, q * PP + k4 * 4, v);
            }
        }
        // V chunk [64 k][96 c] fp32 -> split
        {
            const float* Vg = g_V + ((size_t)b * LSEQ + k0) * CH;
#pragma unroll
            for (int j = 0; j < 6; ++j) {
                int idx = tid + j * 256;
                int r = idx / 24, c4 = idx % 24;
                float4 v = *(const float4*)(Vg + r * CH + c4 * 4);
                split4(Vh, Vl, r * VP + c4 * 4, v);
            }
        }
        __syncthreads();

#pragma unroll
        for (int ks = 0; ks < 4; ++ks) {
            const uint32_t akc = ks * 32;              // A col advance: 16 bf16
            const uint32_t bkr = ks * 16 * (VP * 2);   // B row advance: 16 k rows
            uint32_t A[2][4], L[2][4], Bf[6][2];
#pragma unroll
            for (int mf = 0; mf < 2; ++mf) ldsm4(A[mf], PhS + aoff + mf * 16 * (PP * 2) + akc);
#pragma unroll
            for (int nf = 0; nf < 6; ++nf) ldsm2t(Bf[nf], VhS + bkr + brow + bcol + nf * 16);
#pragma unroll
            for (int mf = 0; mf < 2; ++mf)
#pragma unroll
                for (int nf = 0; nf < 6; ++nf) mma_bf16(D[mf][nf], A[mf], Bf[nf]);
#pragma unroll
            for (int mf = 0; mf < 2; ++mf) ldsm4(L[mf], PlS + aoff + mf * 16 * (PP * 2) + akc);
#pragma unroll
            for (int mf = 0; mf < 2; ++mf)
#pragma unroll
                for (int nf = 0; nf < 6; ++nf) mma_bf16(D[mf][nf], L[mf], Bf[nf]);
#pragma unroll
            for (int nf = 0; nf < 6; ++nf) ldsm2t(Bf[nf], VlS + bkr + brow + bcol + nf * 16);
#pragma unroll
            for (int mf = 0; mf < 2; ++mf)
#pragma unroll
                for (int nf = 0; nf < 6; ++nf) mma_bf16(D[mf][nf], A[mf], Bf[nf]);
        }
    }

    // epilogue: write O[b, q, c]
    float* Og = g_O + ((size_t)b * LSEQ + q0) * CH;
#pragma unroll
    for (int mf = 0; mf < 2; ++mf) {
        int row = wm * 32 + mf * 16 + gr;
#pragma unroll
        for (int nf = 0; nf < 6; ++nf) {
            int col = wn * 48 + nf * 8 + c2;
            *(float2*)(Og + (size_t)row * CH + col) = make_float2(D[mf][nf][0], D[mf][nf][1]);
            *(float2*)(Og + (size_t)(row + 8) * CH + col) = make_float2(D[mf][nf][2], D[mf][nf][3]);
        }
    }
}

// ============================================================================
// Kernel 5: y[b,o,l] = gamma * sum_c Wlast[o,c]*O[b,l,c] + x[b,o,l]
// ============================================================================
__global__ __launch_bounds__(256, 2) void out_kernel(
    const float* __restrict__ x,
    const float* __restrict__ Wlast,
    const float* __restrict__ gammap,
    float* __restrict__ out)
{
    extern __shared__ char raw[];
    float (*Os)[97]  = (float(*)[97])raw;
    float (*Wls)[96] = (float(*)[96])(raw + 64 * 97 * 4);

    const int l0  = blockIdx.x * 64;
    const int o0  = blockIdx.y * 96;
    const int b   = blockIdx.z;
    const int tid = threadIdx.x;
    const int og  = tid >> 4;
    const int lg  = tid & 15;
    const float gamma = gammap[0];

    {
        int i = tid;
#pragma unroll
        for (int it = 0; it < 6; ++it, i += 256) {
            int q = i / 24, c4 = i % 24;
            float4 v = *(const float4*)(g_O + ((size_t)b * LSEQ + l0 + q) * CH + c4 * 4);
            Os[q][c4 * 4 + 0] = v.x;
            Os[q][c4 * 4 + 1] = v.y;
            Os[q][c4 * 4 + 2] = v.z;
            Os[q][c4 * 4 + 3] = v.w;
        }
    }
    {
        int i = tid;
#pragma unroll
        for (int it = 0; it < 9; ++it, i += 256) {
            int o = i % 96, c4 = i / 96;
            float4 v = *(const float4*)(Wlast + (size_t)(o0 + o) * CH + c4 * 4);
            Wls[c4 * 4 + 0][o] = v.x;
            Wls[c4 * 4 + 1][o] = v.y;
            Wls[c4 * 4 + 2][o] = v.z;
            Wls[c4 * 4 + 3][o] = v.w;
        }
    }
    __syncthreads();

    float acc[6][4];
#pragma unroll
    for (int j = 0; j < 6; ++j)
#pragma unroll
        for (int i = 0; i < 4; ++i) acc[j][i] = 0.f;

#pragma unroll 4
    for (int c = 0; c < CH; ++c) {
        float av[4];
        av[0] = Os[lg * 4 + 0][c];
        av[1] = Os[lg * 4 + 1][c];
        av[2] = Os[lg * 4 + 2][c];
        av[3] = Os[lg * 4 + 3][c];
        float2 w0 = *(const float2*)&Wls[c][og * 6];
        float2 w1 = *(const float2*)&Wls[c][og * 6 + 2];
        float2 w2 = *(const float2*)&Wls[c][og * 6 + 4];
        float wv[6] = {w0.x, w0.y, w1.x, w1.y, w2.x, w2.y};
#pragma unroll
        for (int j = 0; j < 6; ++j)
#pragma unroll
            for (int i = 0; i < 4; ++i) acc[j][i] += wv[j] * av[i];
    }

#pragma unroll
    for (int j = 0; j < 6; ++j) {
        size_t bbase = (size_t)b * COUTC * LSEQ + (size_t)(o0 + og * 6 + j) * LSEQ + l0 + lg * 4;
        float4 xr = *(const float4*)(x + bbase);
        float4 yv = make_float4(gamma * acc[j][0] + xr.x,
                                gamma * acc[j][1] + xr.y,
                                gamma * acc[j][2] + xr.z,
                                gamma * acc[j][3] + xr.w);
        *(float4*)(out + bbase) = yv;
    }
}

// ============================================================================
extern "C" void kernel_launch(void* const* d_in, const int* in_sizes, int n_in,
                              void* d_out, int out_size) {
    const float* x     = (const float*)d_in[0];
    const float* Wq    = (const float*)d_in[1];
    const float* Wk    = (const float*)d_in[2];
    const float* Wv    = (const float*)d_in[3];
    const float* Wl    = (const float*)d_in[4];
    const float* gamma = (const float*)d_in[5];
    float* out = (float*)d_out;

    cudaFuncSetAttribute(score_kernel, cudaFuncAttributeMaxDynamicSharedMemorySize, SC_SMEM);
    cudaFuncSetAttribute(pv_kernel,    cudaFuncAttributeMaxDynamicSharedMemorySize, PV_SMEM);
    cudaFuncSetAttribute(out_kernel,   cudaFuncAttributeMaxDynamicSharedMemorySize,
                         64 * 97 * 4 + 96 * 96 * 4);

    proj_kernel<<<dim3(64, 3, 8), 256>>>(x, Wq, Wk, Wv);
    score_kernel<<<dim3(32, 8), 256, SC_SMEM>>>();
    softmax_kernel<<<BB * LSEQ, 128>>>();
    pv_kernel<<<dim3(32, 8), 256, PV_SMEM>>>();
    out_kernel<<<dim3(64, 8, 8), 256, 64 * 97 * 4 + 96 * 96 * 4>>>(x, Wl, gamma, out);
}

// round 5
// speedup vs baseline: 2.5318x; 1.4727x over previous
#include <cuda_runtime.h>
#include <cuda_bf16.h>
#include <cstdint>
#include <cstddef>

#define BB    8
#define CIN   768
#define LSEQ  4096
#define CH    96
#define COUTC 768

// ---- device-global scratch ----
__device__ float g_Q[BB * LSEQ * CH];
__device__ float g_K[BB * LSEQ * CH];
__device__ float g_V[BB * LSEQ * CH];
__device__ float g_O[BB * LSEQ * CH];

// ============================================================================
// PTX helpers
// ============================================================================
__device__ __forceinline__ uint32_t s2u(const void* p) {
    return (uint32_t)__cvta_generic_to_shared(p);
}
__device__ __forceinline__ void ldsm4(uint32_t r[4], uint32_t a) {
    asm volatile("ldmatrix.sync.aligned.m8n8.x4.shared.b16 {%0,%1,%2,%3}, [%4];"
                 : "=r"(r[0]), "=r"(r[1]), "=r"(r[2]), "=r"(r[3]) : "r"(a));
}
__device__ __forceinline__ void ldsm4t(uint32_t r[4], uint32_t a) {
    asm volatile("ldmatrix.sync.aligned.m8n8.x4.trans.shared.b16 {%0,%1,%2,%3}, [%4];"
                 : "=r"(r[0]), "=r"(r[1]), "=r"(r[2]), "=r"(r[3]) : "r"(a));
}
__device__ __forceinline__ void ldsm2(uint32_t r[2], uint32_t a) {
    asm volatile("ldmatrix.sync.aligned.m8n8.x2.shared.b16 {%0,%1}, [%2];"
                 : "=r"(r[0]), "=r"(r[1]) : "r"(a));
}
__device__ __forceinline__ void ldsm2t(uint32_t r[2], uint32_t a) {
    asm volatile("ldmatrix.sync.aligned.m8n8.x2.trans.shared.b16 {%0,%1}, [%2];"
                 : "=r"(r[0]), "=r"(r[1]) : "r"(a));
}
__device__ __forceinline__ void mma_bf16(float d[4], const uint32_t a[4], const uint32_t b[2]) {
    asm volatile("mma.sync.aligned.m16n8k16.row.col.f32.bf16.bf16.f32 "
                 "{%0,%1,%2,%3}, {%4,%5,%6,%7}, {%8,%9}, {%0,%1,%2,%3};"
                 : "+f"(d[0]), "+f"(d[1]), "+f"(d[2]), "+f"(d[3])
                 : "r"(a[0]), "r"(a[1]), "r"(a[2]), "r"(a[3]), "r"(b[0]), "r"(b[1]));
}
// split fp32x4 -> bf16 hi/lo, packed 8B stores (eoff multiple of 4)
__device__ __forceinline__ void split4(__nv_bfloat16* hiB, __nv_bfloat16* loB,
                                       int eoff, float4 v) {
    float f[4] = {v.x, v.y, v.z, v.w};
    unsigned short h[4], l[4];
#pragma unroll
    for (int i = 0; i < 4; ++i) {
        __nv_bfloat16 hb = __float2bfloat16(f[i]);
        float r = f[i] - __bfloat162float(hb);
        h[i] = __bfloat16_as_ushort(hb);
        l[i] = __bfloat16_as_ushort(__float2bfloat16(r));
    }
    *(uint2*)(hiB + eoff) = make_uint2((uint32_t)h[0] | ((uint32_t)h[1] << 16),
                                       (uint32_t)h[2] | ((uint32_t)h[3] << 16));
    *(uint2*)(loB + eoff) = make_uint2((uint32_t)l[0] | ((uint32_t)l[1] << 16),
                                       (uint32_t)l[2] | ((uint32_t)l[3] << 16));
}
// pack two floats into bf16x2 hi + residual lo
__device__ __forceinline__ void split2pack(float a, float b, uint32_t& hi, uint32_t& lo) {
    __nv_bfloat16 ah = __float2bfloat16(a), bh = __float2bfloat16(b);
    float ar = a - __bfloat162float(ah);
    float br = b - __bfloat162float(bh);
    hi = (uint32_t)__bfloat16_as_ushort(ah) | ((uint32_t)__bfloat16_as_ushort(bh) << 16);
    lo = (uint32_t)__bfloat16_as_ushort(__float2bfloat16(ar)) |
         ((uint32_t)__bfloat16_as_ushort(__float2bfloat16(br)) << 16);
}
// FFMA-only exp (x <= 0)
__device__ __forceinline__ float fexp(float x) {
    float y = x * 1.4426950408889634f;
    y = fmaxf(y, -126.0f);
    float t = y + 12582912.0f;
    float f = y - (t - 12582912.0f);
    float p =            1.3333558146e-3f;
    p = fmaf(p, f, 9.6181291076e-3f);
    p = fmaf(p, f, 5.5504108664e-2f);
    p = fmaf(p, f, 2.4022650696e-1f);
    p = fmaf(p, f, 6.9314718056e-1f);
    p = fmaf(p, f, 1.0f);
    int e = (__float_as_int(t) - 0x4b400000 + 127) << 23;
    return p * __int_as_float(e);
}

// ============================================================================
// Kernel 1: QKV projection via mma.sync split-bf16.
// out[b,l,o] = sum_c x[b,c,l] * W[o,c].  CTA: 128 l x 96 o, chunks of 64 c.
// A = x^T via ldmatrix.trans on [c][l] smem; B = W via normal ldsm.
// 8 warps = 2(l) x 4(o); warp tile 64l x 24o.
// ============================================================================
#define XP 136     // x smem pitch (bf16 elems): 272B rows -> stride 16 mod 128
#define WPT 72     // W smem pitch
#define PJ_SMEM (2 * 64 * XP * 2 + 2 * 96 * WPT * 2)   // 62464 B

__global__ __launch_bounds__(256, 2) void projmma_kernel(
    const float* __restrict__ x,
    const float* __restrict__ Wq,
    const float* __restrict__ Wk,
    const float* __restrict__ Wv)
{
    extern __shared__ char smraw[];
    __nv_bfloat16* Xh = (__nv_bfloat16*)smraw;
    __nv_bfloat16* Xl = Xh + 64 * XP;
    __nv_bfloat16* Wh = Xl + 64 * XP;
    __nv_bfloat16* Wl2 = Wh + 96 * WPT;

    const int l0 = blockIdx.x * 128;
    const int b  = blockIdx.z;
    const float* W;
    float* Out;
    if (blockIdx.y == 0)      { W = Wq; Out = g_Q; }
    else if (blockIdx.y == 1) { W = Wk; Out = g_K; }
    else                      { W = Wv; Out = g_V; }

    const int tid = threadIdx.x, wid = tid >> 5, lane = tid & 31;
    const int wm = wid & 1, wn = wid >> 1;

    const uint32_t XhS = s2u(Xh), XlS = s2u(Xl), WhS = s2u(Wh), WlS = s2u(Wl2);
    const int gr = lane >> 2, c2 = (lane & 3) * 2;
    // A (trans) lane addressing: k-row = (lane&7) + ((lane>>4)<<3), m-col half = ((lane>>3)&1)*8
    const uint32_t kla = (lane & 7) + ((lane >> 4) << 3);
    const uint32_t mla = ((lane >> 3) & 1) * 8 + wm * 64;
    // B lane addressing (as in score kernel)
    const uint32_t bofs = ((wn * 24 + (lane & 7)) * WPT + (((lane >> 3) & 1) << 3)) * 2;

    float D[4][3][4];
#pragma unroll
    for (int mf = 0; mf < 4; ++mf)
#pragma unroll
        for (int nf = 0; nf < 3; ++nf)
#pragma unroll
            for (int e = 0; e < 4; ++e) D[mf][nf][e] = 0.f;

    const float* xb = x + (size_t)b * CIN * LSEQ + l0;

    for (int c0 = 0; c0 < CIN; c0 += 64) {
        __syncthreads();
        // x chunk [64 c][128 l] -> split bf16, natural [c][l]
#pragma unroll
        for (int it = 0; it < 8; ++it) {
            int idx = tid + it * 256;
            int c = idx >> 5, l4 = idx & 31;
            float4 v = *(const float4*)(xb + (size_t)(c0 + c) * LSEQ + l4 * 4);
            split4(Xh, Xl, c * XP + l4 * 4, v);
        }
        // W chunk [96 o][64 c] -> split bf16
#pragma unroll
        for (int it = 0; it < 6; ++it) {
            int idx = tid + it * 256;
            int o = idx >> 4, c4 = idx & 15;
            float4 v = *(const float4*)(W + o * CIN + c0 + c4 * 4);
            split4(Wh, Wl2, o * WPT + c4 * 4, v);
        }
        __syncthreads();

#pragma unroll
        for (int ks = 0; ks < 4; ++ks) {
            uint32_t A[4][4], L[4][4], Bf[3][2];
            const uint32_t arow = (ks * 16 + kla) * XP;
#pragma unroll
            for (int mf = 0; mf < 4; ++mf)
                ldsm4t(A[mf], XhS + (arow + mla + mf * 16) * 2);
#pragma unroll
            for (int nf = 0; nf < 3; ++nf)
                ldsm2(Bf[nf], WhS + bofs + nf * 8 * (WPT * 2) + ks * 32);
#pragma unroll
            for (int mf = 0; mf < 4; ++mf)
#pragma unroll
                for (int nf = 0; nf < 3; ++nf) mma_bf16(D[mf][nf], A[mf], Bf[nf]);
#pragma unroll
            for (int mf = 0; mf < 4; ++mf)
                ldsm4t(L[mf], XlS + (arow + mla + mf * 16) * 2);
#pragma unroll
            for (int mf = 0; mf < 4; ++mf)
#pragma unroll
                for (int nf = 0; nf < 3; ++nf) mma_bf16(D[mf][nf], L[mf], Bf[nf]);
#pragma unroll
            for (int nf = 0; nf < 3; ++nf)
                ldsm2(Bf[nf], WlS + bofs + nf * 8 * (WPT * 2) + ks * 32);
#pragma unroll
            for (int mf = 0; mf < 4; ++mf)
#pragma unroll
                for (int nf = 0; nf < 3; ++nf) mma_bf16(D[mf][nf], A[mf], Bf[nf]);
        }
    }

    // epilogue: Out[b, l0+row, col]
#pragma unroll
    for (int mf = 0; mf < 4; ++mf) {
        int row = wm * 64 + mf * 16 + gr;
        float* dst = Out + ((size_t)b * LSEQ + l0 + row) * CH;
#pragma unroll
        for (int nf = 0; nf < 3; ++nf) {
            int col = wn * 24 + nf * 8 + c2;
            *(float2*)(dst + col) = make_float2(D[mf][nf][0], D[mf][nf][1]);
            *(float2*)(dst + 8 * CH + col) = make_float2(D[mf][nf][2], D[mf][nf][3]);
        }
    }
}

// ============================================================================
// Kernel 2: fused flash attention (split-bf16 mma.sync, online softmax).
// CTA: 128 q, 8 warps x 16 q each. K/V chunks of 64 keys.
// Q frags persistent in registers; P passed register-to-register (FA2 layout).
// ============================================================================
#define FAP 104
#define FA_SMEM (4 * 64 * FAP * 2)    // Kh,Kl,Vh,Vl = 53248 B

__global__ __launch_bounds__(256, 1) void fattn_kernel() {
    extern __shared__ char smraw[];
    __nv_bfloat16* Kh = (__nv_bfloat16*)smraw;
    __nv_bfloat16* Kl = Kh + 64 * FAP;
    __nv_bfloat16* Vh = Kl + 64 * FAP;
    __nv_bfloat16* Vl = Vh + 64 * FAP;

    const int tid = threadIdx.x, wid = tid >> 5, lane = tid & 31;
    const int b = blockIdx.y, q0 = blockIdx.x * 128;
    const int gr = lane >> 2, c2 = (lane & 3) * 2;

    const uint32_t KhS = s2u(Kh), KlS = s2u(Kl), VhS = s2u(Vh), VlS = s2u(Vl);

    // ---- stage Q (split) through the K/V smem regions, build persistent frags
    {
        const float* Qg = g_Q + ((size_t)b * LSEQ + q0) * CH;
#pragma unroll
        for (int it = 0; it < 12; ++it) {
            int idx = tid + it * 256;
            int r = idx / 24, c4 = idx % 24;
            float4 v = *(const float4*)(Qg + r * CH + c4 * 4);
            __nv_bfloat16* hb = (r < 64) ? Kh : Kl;   // Q-hi halves
            __nv_bfloat16* lb = (r < 64) ? Vh : Vl;   // Q-lo halves
            split4(hb, lb, (r & 63) * FAP + c4 * 4, v);
        }
    }
    __syncthreads();

    uint32_t QH[6][4], QL[6][4];
    {
        const uint32_t hbase = (wid < 4) ? KhS : KlS;
        const uint32_t lbase = (wid < 4) ? VhS : VlS;
        const uint32_t arow = (((wid & 3) * 16 + (lane & 15)) * FAP + ((lane >> 4) << 3)) * 2;
#pragma unroll
        for (int ks = 0; ks < 6; ++ks) {
            ldsm4(QH[ks], hbase + arow + ks * 32);
            ldsm4(QL[ks], lbase + arow + ks * 32);
        }
    }

    float O[12][4];
#pragma unroll
    for (int nf = 0; nf < 12; ++nf)
#pragma unroll
        for (int e = 0; e < 4; ++e) O[nf][e] = 0.f;
    float m0 = -1e30f, m1 = -1e30f, l0s = 0.f, l1s = 0.f;

    const float* Kg = g_K + (size_t)b * LSEQ * CH;
    const float* Vg = g_V + (size_t)b * LSEQ * CH;
    const uint32_t bofsK = ((lane & 7) * FAP + (((lane >> 3) & 1) << 3)) * 2;
    const uint32_t browV = (lane & 15) * (FAP * 2);

    for (int ct = 0; ct < 64; ++ct) {
        const int k0 = ct * 64;
        __syncthreads();
#pragma unroll
        for (int it = 0; it < 6; ++it) {
            int idx = tid + it * 256;
            int r = idx / 24, c4 = idx % 24;
            float4 v = *(const float4*)(Kg + (size_t)(k0 + r) * CH + c4 * 4);
            split4(Kh, Kl, r * FAP + c4 * 4, v);
        }
#pragma unroll
        for (int it = 0; it < 6; ++it) {
            int idx = tid + it * 256;
            int r = idx / 24, c4 = idx % 24;
            float4 v = *(const float4*)(Vg + (size_t)(k0 + r) * CH + c4 * 4);
            split4(Vh, Vl, r * FAP + c4 * 4, v);
        }
        __syncthreads();

        // ---- S = Q K^T (split-3), warp tile 16 x 64
        float S[8][4];
#pragma unroll
        for (int nf = 0; nf < 8; ++nf)
#pragma unroll
            for (int e = 0; e < 4; ++e) S[nf][e] = 0.f;

#pragma unroll
        for (int ks = 0; ks < 6; ++ks) {
            uint32_t Bf[8][2];
#pragma unroll
            for (int nf = 0; nf < 8; ++nf)
                ldsm2(Bf[nf], KhS + bofsK + nf * 8 * (FAP * 2) + ks * 32);
#pragma unroll
            for (int nf = 0; nf < 8; ++nf) mma_bf16(S[nf], QH[ks], Bf[nf]);
#pragma unroll
            for (int nf = 0; nf < 8; ++nf) mma_bf16(S[nf], QL[ks], Bf[nf]);
#pragma unroll
            for (int nf = 0; nf < 8; ++nf)
                ldsm2(Bf[nf], KlS + bofsK + nf * 8 * (FAP * 2) + ks * 32);
#pragma unroll
            for (int nf = 0; nf < 8; ++nf) mma_bf16(S[nf], QH[ks], Bf[nf]);
        }

        // ---- online softmax (rows gr and gr+8; 4 lanes share a row)
        float r0 = -1e30f, r1 = -1e30f;
#pragma unroll
        for (int nf = 0; nf < 8; ++nf) {
            r0 = fmaxf(r0, fmaxf(S[nf][0], S[nf][1]));
            r1 = fmaxf(r1, fmaxf(S[nf][2], S[nf][3]));
        }
        r0 = fmaxf(r0, __shfl_xor_sync(0xffffffffu, r0, 1));
        r0 = fmaxf(r0, __shfl_xor_sync(0xffffffffu, r0, 2));
        r1 = fmaxf(r1, __shfl_xor_sync(0xffffffffu, r1, 1));
        r1 = fmaxf(r1, __shfl_xor_sync(0xffffffffu, r1, 2));
        const float nm0 = fmaxf(m0, r0), nm1 = fmaxf(m1, r1);
        const float sc0 = fexp(m0 - nm0), sc1 = fexp(m1 - nm1);
        m0 = nm0; m1 = nm1;

        float ps0 = 0.f, ps1 = 0.f;
#pragma unroll
        for (int nf = 0; nf < 8; ++nf) {
            S[nf][0] = fexp(S[nf][0] - m0);
            S[nf][1] = fexp(S[nf][1] - m0);
            S[nf][2] = fexp(S[nf][2] - m1);
            S[nf][3] = fexp(S[nf][3] - m1);
            ps0 += S[nf][0] + S[nf][1];
            ps1 += S[nf][2] + S[nf][3];
        }
        ps0 += __shfl_xor_sync(0xffffffffu, ps0, 1);
        ps0 += __shfl_xor_sync(0xffffffffu, ps0, 2);
        ps1 += __shfl_xor_sync(0xffffffffu, ps1, 1);
        ps1 += __shfl_xor_sync(0xffffffffu, ps1, 2);
        l0s = l0s * sc0 + ps0;
        l1s = l1s * sc1 + ps1;
#pragma unroll
        for (int nf = 0; nf < 12; ++nf) {
            O[nf][0] *= sc0; O[nf][1] *= sc0;
            O[nf][2] *= sc1; O[nf][3] *= sc1;
        }

        // ---- P frags (register-to-register, FA2 layout) split hi/lo
        uint32_t PH[4][4], PL[4][4];
#pragma unroll
        for (int ks = 0; ks < 4; ++ks) {
            split2pack(S[2 * ks][0],     S[2 * ks][1],     PH[ks][0], PL[ks][0]);
            split2pack(S[2 * ks][2],     S[2 * ks][3],     PH[ks][1], PL[ks][1]);
            split2pack(S[2 * ks + 1][0], S[2 * ks + 1][1], PH[ks][2], PL[ks][2]);
            split2pack(S[2 * ks + 1][2], S[2 * ks + 1][3], PH[ks][3], PL[ks][3]);
        }

        // ---- O += P V (split-3)
#pragma unroll
        for (int ks = 0; ks < 4; ++ks) {
            uint32_t Vf[12][2];
            const uint32_t vkr = ks * 16 * (FAP * 2) + browV;
#pragma unroll
            for (int nf = 0; nf < 12; ++nf) ldsm2t(Vf[nf], VhS + vkr + nf * 16);
#pragma unroll
            for (int nf = 0; nf < 12; ++nf) mma_bf16(O[nf], PH[ks], Vf[nf]);
#pragma unroll
            for (int nf = 0; nf < 12; ++nf) mma_bf16(O[nf], PL[ks], Vf[nf]);
#pragma unroll
            for (int nf = 0; nf < 12; ++nf) ldsm2t(Vf[nf], VlS + vkr + nf * 16);
#pragma unroll
            for (int nf = 0; nf < 12; ++nf) mma_bf16(O[nf], PH[ks], Vf[nf]);
        }
    }

    // ---- epilogue: O /= l, write g_O[b, q, c]
    const float i0 = 1.f / l0s, i1 = 1.f / l1s;
    float* Og = g_O + ((size_t)b * LSEQ + q0 + wid * 16) * CH;
#pragma unroll
    for (int nf = 0; nf < 12; ++nf) {
        int col = nf * 8 + c2;
        *(float2*)(Og + (size_t)gr * CH + col) = make_float2(O[nf][0] * i0, O[nf][1] * i0);
        *(float2*)(Og + (size_t)(gr + 8) * CH + col) = make_float2(O[nf][2] * i1, O[nf][3] * i1);
    }
}

// ============================================================================
// Kernel 3: y[b,o,l] = gamma * sum_c Wlast[o,c]*O[b,l,c] + x[b,o,l]
// ============================================================================
__global__ __launch_bounds__(256, 2) void out_kernel(
    const float* __restrict__ x,
    const float* __restrict__ Wlast,
    const float* __restrict__ gammap,
    float* __restrict__ out)
{
    extern __shared__ char raw[];
    float (*Os)[97]  = (float(*)[97])raw;
    float (*Wls)[96] = (float(*)[96])(raw + 64 * 97 * 4);

    const int l0  = blockIdx.x * 64;
    const int o0  = blockIdx.y * 96;
    const int b   = blockIdx.z;
    const int tid = threadIdx.x;
    const int og  = tid >> 4;
    const int lg  = tid & 15;
    const float gamma = gammap[0];

    {
        int i = tid;
#pragma unroll
        for (int it = 0; it < 6; ++it, i += 256) {
            int q = i / 24, c4 = i % 24;
            float4 v = *(const float4*)(g_O + ((size_t)b * LSEQ + l0 + q) * CH + c4 * 4);
            Os[q][c4 * 4 + 0] = v.x;
            Os[q][c4 * 4 + 1] = v.y;
            Os[q][c4 * 4 + 2] = v.z;
            Os[q][c4 * 4 + 3] = v.w;
        }
    }
    {
        int i = tid;
#pragma unroll
        for (int it = 0; it < 9; ++it, i += 256) {
            int o = i % 96, c4 = i / 96;
            float4 v = *(const float4*)(Wlast + (size_t)(o0 + o) * CH + c4 * 4);
            Wls[c4 * 4 + 0][o] = v.x;
            Wls[c4 * 4 + 1][o] = v.y;
            Wls[c4 * 4 + 2][o] = v.z;
            Wls[c4 * 4 + 3][o] = v.w;
        }
    }
    __syncthreads();

    float acc[6][4];
#pragma unroll
    for (int j = 0; j < 6; ++j)
#pragma unroll
        for (int i = 0; i < 4; ++i) acc[j][i] = 0.f;

#pragma unroll 4
    for (int c = 0; c < CH; ++c) {
        float av[4];
        av[0] = Os[lg * 4 + 0][c];
        av[1] = Os[lg * 4 + 1][c];
        av[2] = Os[lg * 4 + 2][c];
        av[3] = Os[lg * 4 + 3][c];
        float2 w0 = *(const float2*)&Wls[c][og * 6];
        float2 w1 = *(const float2*)&Wls[c][og * 6 + 2];
        float2 w2 = *(const float2*)&Wls[c][og * 6 + 4];
        float wv[6] = {w0.x, w0.y, w1.x, w1.y, w2.x, w2.y};
#pragma unroll
        for (int j = 0; j < 6; ++j)
#pragma unroll
            for (int i = 0; i < 4; ++i) acc[j][i] += wv[j] * av[i];
    }

#pragma unroll
    for (int j = 0; j < 6; ++j) {
        size_t bbase = (size_t)b * COUTC * LSEQ + (size_t)(o0 + og * 6 + j) * LSEQ + l0 + lg * 4;
        float4 xr = *(const float4*)(x + bbase);
        float4 yv = make_float4(gamma * acc[j][0] + xr.x,
                                gamma * acc[j][1] + xr.y,
                                gamma * acc[j][2] + xr.z,
                                gamma * acc[j][3] + xr.w);
        *(float4*)(out + bbase) = yv;
    }
}

// ============================================================================
extern "C" void kernel_launch(void* const* d_in, const int* in_sizes, int n_in,
                              void* d_out, int out_size) {
    const float* x     = (const float*)d_in[0];
    const float* Wq    = (const float*)d_in[1];
    const float* Wk    = (const float*)d_in[2];
    const float* Wv    = (const float*)d_in[3];
    const float* Wl    = (const float*)d_in[4];
    const float* gamma = (const float*)d_in[5];
    float* out = (float*)d_out;

    cudaFuncSetAttribute(projmma_kernel, cudaFuncAttributeMaxDynamicSharedMemorySize, PJ_SMEM);
    cudaFuncSetAttribute(fattn_kernel,   cudaFuncAttributeMaxDynamicSharedMemorySize, FA_SMEM);
    cudaFuncSetAttribute(out_kernel,     cudaFuncAttributeMaxDynamicSharedMemorySize,
                         64 * 97 * 4 + 96 * 96 * 4);

    projmma_kernel<<<dim3(32, 3, 8), 256, PJ_SMEM>>>(x, Wq, Wk, Wv);
    fattn_kernel<<<dim3(32, 8), 256, FA_SMEM>>>();
    out_kernel<<<dim3(64, 8, 8), 256, 64 * 97 * 4 + 96 * 96 * 4>>>(x, Wl, gamma, out);
}

// round 7
// speedup vs baseline: 3.1553x; 1.2463x over previous
#include <cuda_runtime.h>
#include <cuda_bf16.h>
#include <cstdint>
#include <cstddef>

#define BB    8
#define CIN   768
#define LSEQ  4096
#define CH    96
#define COUTC 768

// ---- device-global scratch: pre-split bf16 hi/lo pairs ----
__device__ __nv_bfloat16 g_Qh[BB * LSEQ * CH], g_Ql[BB * LSEQ * CH];
__device__ __nv_bfloat16 g_Kh[BB * LSEQ * CH], g_Kl[BB * LSEQ * CH];
__device__ __nv_bfloat16 g_Vh[BB * LSEQ * CH], g_Vl[BB * LSEQ * CH];
__device__ __nv_bfloat16 g_Oh[BB * LSEQ * CH], g_Ol[BB * LSEQ * CH];
__device__ __nv_bfloat16 g_Wh[COUTC * CH],     g_Wl[COUTC * CH];

// ============================================================================
// PTX helpers
// ============================================================================
__device__ __forceinline__ uint32_t s2u(const void* p) {
    return (uint32_t)__cvta_generic_to_shared(p);
}
__device__ __forceinline__ void ldsm4(uint32_t r[4], uint32_t a) {
    asm volatile("ldmatrix.sync.aligned.m8n8.x4.shared.b16 {%0,%1,%2,%3}, [%4];"
                 : "=r"(r[0]), "=r"(r[1]), "=r"(r[2]), "=r"(r[3]) : "r"(a));
}
__device__ __forceinline__ void ldsm4t(uint32_t r[4], uint32_t a) {
    asm volatile("ldmatrix.sync.aligned.m8n8.x4.trans.shared.b16 {%0,%1,%2,%3}, [%4];"
                 : "=r"(r[0]), "=r"(r[1]), "=r"(r[2]), "=r"(r[3]) : "r"(a));
}
__device__ __forceinline__ void ldsm2(uint32_t r[2], uint32_t a) {
    asm volatile("ldmatrix.sync.aligned.m8n8.x2.shared.b16 {%0,%1}, [%2];"
                 : "=r"(r[0]), "=r"(r[1]) : "r"(a));
}
__device__ __forceinline__ void ldsm2t(uint32_t r[2], uint32_t a) {
    asm volatile("ldmatrix.sync.aligned.m8n8.x2.trans.shared.b16 {%0,%1}, [%2];"
                 : "=r"(r[0]), "=r"(r[1]) : "r"(a));
}
__device__ __forceinline__ void mma_bf16(float d[4], const uint32_t a[4], const uint32_t b[2]) {
    asm volatile("mma.sync.aligned.m16n8k16.row.col.f32.bf16.bf16.f32 "
                 "{%0,%1,%2,%3}, {%4,%5,%6,%7}, {%8,%9}, {%0,%1,%2,%3};"
                 : "+f"(d[0]), "+f"(d[1]), "+f"(d[2]), "+f"(d[3])
                 : "r"(a[0]), "r"(a[1]), "r"(a[2]), "r"(a[3]), "r"(b[0]), "r"(b[1]));
}
__device__ __forceinline__ void cpa16(uint32_t dst, const void* src) {
    asm volatile("cp.async.cg.shared.global [%0], [%1], 16;" :: "r"(dst), "l"(src));
}
#define CP_COMMIT() asm volatile("cp.async.commit_group;" ::: "memory")
#define CP_WAIT0()  asm volatile("cp.async.wait_group 0;" ::: "memory")
#define CP_WAIT1()  asm volatile("cp.async.wait_group 1;" ::: "memory")

// split fp32x4 -> bf16 hi/lo, packed 8B stores
__device__ __forceinline__ void split4(__nv_bfloat16* hiB, __nv_bfloat16* loB,
                                       int eoff, float4 v) {
    float f[4] = {v.x, v.y, v.z, v.w};
    unsigned short h[4], l[4];
#pragma unroll
    for (int i = 0; i < 4; ++i) {
        __nv_bfloat16 hb = __float2bfloat16(f[i]);
        float r = f[i] - __bfloat162float(hb);
        h[i] = __bfloat16_as_ushort(hb);
        l[i] = __bfloat16_as_ushort(__float2bfloat16(r));
    }
    *(uint2*)(hiB + eoff) = make_uint2((uint32_t)h[0] | ((uint32_t)h[1] << 16),
                                       (uint32_t)h[2] | ((uint32_t)h[3] << 16));
    *(uint2*)(loB + eoff) = make_uint2((uint32_t)l[0] | ((uint32_t)l[1] << 16),
                                       (uint32_t)l[2] | ((uint32_t)l[3] << 16));
}
__device__ __forceinline__ void split2pack(float a, float b, uint32_t& hi, uint32_t& lo) {
    __nv_bfloat16 ah = __float2bfloat16(a), bh = __float2bfloat16(b);
    float ar = a - __bfloat162float(ah);
    float br = b - __bfloat162float(bh);
    hi = (uint32_t)__bfloat16_as_ushort(ah) | ((uint32_t)__bfloat16_as_ushort(bh) << 16);
    lo = (uint32_t)__bfloat16_as_ushort(__float2bfloat16(ar)) |
         ((uint32_t)__bfloat16_as_ushort(__float2bfloat16(br)) << 16);
}
// FFMA-only exp (x <= 0)
__device__ __forceinline__ float fexp(float x) {
    float y = x * 1.4426950408889634f;
    y = fmaxf(y, -126.0f);
    float t = y + 12582912.0f;
    float f = y - (t - 12582912.0f);
    float p =            1.3333558146e-3f;
    p = fmaf(p, f, 9.6181291076e-3f);
    p = fmaf(p, f, 5.5504108664e-2f);
    p = fmaf(p, f, 2.4022650696e-1f);
    p = fmaf(p, f, 6.9314718056e-1f);
    p = fmaf(p, f, 1.0f);
    int e = (__float_as_int(t) - 0x4b400000 + 127) << 23;
    return p * __int_as_float(e);
}

// ============================================================================
// Kernel 0: split Wlast into bf16 hi/lo (tiny streaming pass)
// ============================================================================
__global__ __launch_bounds__(256) void wsplit_kernel(const float* __restrict__ Wl) {
    int idx = blockIdx.x * 256 + threadIdx.x;     // 18432 threads, 1 float4 each
    float4 v = *(const float4*)(Wl + idx * 4);
    split4(g_Wh, g_Wl, idx * 4, v);
}

// ============================================================================
// Kernel 1: QKV projection via mma.sync split-bf16; outputs pre-split hi/lo.
// ============================================================================
#define XP 136
#define WPT 72
#define PJ_SMEM (2 * 64 * XP * 2 + 2 * 96 * WPT * 2)

__global__ __launch_bounds__(256, 2) void projmma_kernel(
    const float* __restrict__ x,
    const float* __restrict__ Wq,
    const float* __restrict__ Wk,
    const float* __restrict__ Wv)
{
    extern __shared__ char smraw[];
    __nv_bfloat16* Xh = (__nv_bfloat16*)smraw;
    __nv_bfloat16* Xl = Xh + 64 * XP;
    __nv_bfloat16* Wh = Xl + 64 * XP;
    __nv_bfloat16* Wl2 = Wh + 96 * WPT;

    const int l0 = blockIdx.x * 128;
    const int b  = blockIdx.z;
    const float* W;
    __nv_bfloat16 *Outh, *Outl;
    if (blockIdx.y == 0)      { W = Wq; Outh = g_Qh; Outl = g_Ql; }
    else if (blockIdx.y == 1) { W = Wk; Outh = g_Kh; Outl = g_Kl; }
    else                      { W = Wv; Outh = g_Vh; Outl = g_Vl; }

    const int tid = threadIdx.x, wid = tid >> 5, lane = tid & 31;
    const int wm = wid & 1, wn = wid >> 1;

    const uint32_t XhS = s2u(Xh), XlS = s2u(Xl), WhS = s2u(Wh), WlS = s2u(Wl2);
    const int gr = lane >> 2, c2 = (lane & 3) * 2;
    const uint32_t kla = (lane & 7) + ((lane >> 4) << 3);
    const uint32_t mla = ((lane >> 3) & 1) * 8 + wm * 64;
    const uint32_t bofs = ((wn * 24 + (lane & 7)) * WPT + (((lane >> 3) & 1) << 3)) * 2;

    float D[4][3][4];
#pragma unroll
    for (int mf = 0; mf < 4; ++mf)
#pragma unroll
        for (int nf = 0; nf < 3; ++nf)
#pragma unroll
            for (int e = 0; e < 4; ++e) D[mf][nf][e] = 0.f;

    const float* xb = x + (size_t)b * CIN * LSEQ + l0;

    for (int c0 = 0; c0 < CIN; c0 += 64) {
        __syncthreads();
#pragma unroll
        for (int it = 0; it < 8; ++it) {
            int idx = tid + it * 256;
            int c = idx >> 5, l4 = idx & 31;
            float4 v = *(const float4*)(xb + (size_t)(c0 + c) * LSEQ + l4 * 4);
            split4(Xh, Xl, c * XP + l4 * 4, v);
        }
#pragma unroll
        for (int it = 0; it < 6; ++it) {
            int idx = tid + it * 256;
            int o = idx >> 4, c4 = idx & 15;
            float4 v = *(const float4*)(W + o * CIN + c0 + c4 * 4);
            split4(Wh, Wl2, o * WPT + c4 * 4, v);
        }
        __syncthreads();

#pragma unroll
        for (int ks = 0; ks < 4; ++ks) {
            uint32_t A[4][4], L[4][4], Bf[3][2];
            const uint32_t arow = (ks * 16 + kla) * XP;
#pragma unroll
            for (int mf = 0; mf < 4; ++mf)
                ldsm4t(A[mf], XhS + (arow + mla + mf * 16) * 2);
#pragma unroll
            for (int nf = 0; nf < 3; ++nf)
                ldsm2(Bf[nf], WhS + bofs + nf * 8 * (WPT * 2) + ks * 32);
#pragma unroll
            for (int mf = 0; mf < 4; ++mf)
#pragma unroll
                for (int nf = 0; nf < 3; ++nf) mma_bf16(D[mf][nf], A[mf], Bf[nf]);
#pragma unroll
            for (int mf = 0; mf < 4; ++mf)
                ldsm4t(L[mf], XlS + (arow + mla + mf * 16) * 2);
#pragma unroll
            for (int mf = 0; mf < 4; ++mf)
#pragma unroll
                for (int nf = 0; nf < 3; ++nf) mma_bf16(D[mf][nf], L[mf], Bf[nf]);
#pragma unroll
            for (int nf = 0; nf < 3; ++nf)
                ldsm2(Bf[nf], WlS + bofs + nf * 8 * (WPT * 2) + ks * 32);
#pragma unroll
            for (int mf = 0; mf < 4; ++mf)
#pragma unroll
                for (int nf = 0; nf < 3; ++nf) mma_bf16(D[mf][nf], A[mf], Bf[nf]);
        }
    }

    // epilogue: split accumulators, write hi/lo bf16
#pragma unroll
    for (int mf = 0; mf < 4; ++mf) {
        int row = wm * 64 + mf * 16 + gr;
        size_t rb = ((size_t)b * LSEQ + l0 + row) * CH;
#pragma unroll
        for (int nf = 0; nf < 3; ++nf) {
            int col = wn * 24 + nf * 8 + c2;
            uint32_t h, l;
            split2pack(D[mf][nf][0], D[mf][nf][1], h, l);
            *(uint32_t*)(Outh + rb + col) = h;
            *(uint32_t*)(Outl + rb + col) = l;
            split2pack(D[mf][nf][2], D[mf][nf][3], h, l);
            *(uint32_t*)(Outh + rb + 8 * CH + col) = h;
            *(uint32_t*)(Outl + rb + 8 * CH + col) = l;
        }
    }
}

// ============================================================================
// Kernel 2: fused flash attention. Pre-split bf16 operands, cp.async
// double-buffered K/V, zero conversions in the hot loop.
// CTA: 128 q, 8 warps x 16 q. K/V chunks of 64 keys.
// smem: Q stage 53248 (buf0) | buffers 2 x {Kh,Kl,Vh,Vl} 64x104 = 2 x 53248
// ============================================================================
#define FAP 104
#define TPB (64 * FAP * 2)            // 13312 per tile
#define FA_SMEM (2 * 4 * TPB)         // 106496

__global__ __launch_bounds__(256, 1) void fattn_kernel() {
    extern __shared__ char smraw[];
    const uint32_t base = s2u(smraw);
    const int tid = threadIdx.x, wid = tid >> 5, lane = tid & 31;
    const int b = blockIdx.y, q0 = blockIdx.x * 128;
    const int gr = lane >> 2, c2 = (lane & 3) * 2;

    // ---- stage Q hi/lo into buf0 region, build persistent fragments
    {
        const __nv_bfloat16* Qh = g_Qh + ((size_t)b * LSEQ + q0) * CH;
        const __nv_bfloat16* Ql = g_Ql + ((size_t)b * LSEQ + q0) * CH;
#pragma unroll
        for (int it = 0; it < 6; ++it) {
            int idx = tid + it * 256;
            int r = idx / 12, c16 = idx % 12;
            cpa16(base + r * 208 + c16 * 16, Qh + (size_t)r * CH + c16 * 8);
            cpa16(base + 26624 + r * 208 + c16 * 16, Ql + (size_t)r * CH + c16 * 8);
        }
        CP_COMMIT();
        CP_WAIT0();
    }
    __syncthreads();

    uint32_t QH[6][4], QL[6][4];
    {
        const uint32_t arow = ((wid * 16 + (lane & 15)) * FAP + ((lane >> 4) << 3)) * 2;
#pragma unroll
        for (int ks = 0; ks < 6; ++ks) {
            ldsm4(QH[ks], base + arow + ks * 32);
            ldsm4(QL[ks], base + 26624 + arow + ks * 32);
        }
    }
    __syncthreads();

    float O[12][4];
#pragma unroll
    for (int nf = 0; nf < 12; ++nf)
#pragma unroll
        for (int e = 0; e < 4; ++e) O[nf][e] = 0.f;
    float m0 = -1e30f, m1 = -1e30f, l0s = 0.f, l1s = 0.f;

    const __nv_bfloat16* srcs[4] = {
        g_Kh + (size_t)b * LSEQ * CH, g_Kl + (size_t)b * LSEQ * CH,
        g_Vh + (size_t)b * LSEQ * CH, g_Vl + (size_t)b * LSEQ * CH };

    const uint32_t bofsK = ((lane & 7) * FAP + (((lane >> 3) & 1) << 3)) * 2;
    const uint32_t browV = (lane & 15) * (FAP * 2);

    // issue one chunk's 4 tiles into a buffer (12 cp.async/thread + commit)
    auto issue = [&](int ct, uint32_t bufbase) {
        const int k0 = (ct & 63) * 64;
#pragma unroll
        for (int it = 0; it < 12; ++it) {
            int idx = tid + it * 256;
            int tile = idx / 768, w = idx % 768;
            int r = w / 12, c16 = w % 12;
            cpa16(bufbase + tile * TPB + r * 208 + c16 * 16,
                  srcs[tile] + (size_t)(k0 + r) * CH + c16 * 8);
        }
        CP_COMMIT();
    };

    issue(0, base);
    issue(1, base + 4 * TPB);

    for (int ct = 0; ct < 64; ++ct) {
        const uint32_t buf = base + (ct & 1) * (4 * TPB);
        CP_WAIT1();
        __syncthreads();

        const uint32_t KhS = buf, KlS = buf + TPB, VhS = buf + 2 * TPB, VlS = buf + 3 * TPB;

        // ---- S = Q K^T (split-3), warp tile 16 x 64
        float S[8][4];
#pragma unroll
        for (int nf = 0; nf < 8; ++nf)
#pragma unroll
            for (int e = 0; e < 4; ++e) S[nf][e] = 0.f;

#pragma unroll
        for (int ks = 0; ks < 6; ++ks) {
            uint32_t Bf[8][2];
#pragma unroll
            for (int nf = 0; nf < 8; ++nf)
                ldsm2(Bf[nf], KhS + bofsK + nf * 8 * (FAP * 2) + ks * 32);
#pragma unroll
            for (int nf = 0; nf < 8; ++nf) mma_bf16(S[nf], QH[ks], Bf[nf]);
#pragma unroll
            for (int nf = 0; nf < 8; ++nf) mma_bf16(S[nf], QL[ks], Bf[nf]);
#pragma unroll
            for (int nf = 0; nf < 8; ++nf)
                ldsm2(Bf[nf], KlS + bofsK + nf * 8 * (FAP * 2) + ks * 32);
#pragma unroll
            for (int nf = 0; nf < 8; ++nf) mma_bf16(S[nf], QH[ks], Bf[nf]);
        }

        // ---- online softmax
        float r0 = -1e30f, r1 = -1e30f;
#pragma unroll
        for (int nf = 0; nf < 8; ++nf) {
            r0 = fmaxf(r0, fmaxf(S[nf][0], S[nf][1]));
            r1 = fmaxf(r1, fmaxf(S[nf][2], S[nf][3]));
        }
        r0 = fmaxf(r0, __shfl_xor_sync(0xffffffffu, r0, 1));
        r0 = fmaxf(r0, __shfl_xor_sync(0xffffffffu, r0, 2));
        r1 = fmaxf(r1, __shfl_xor_sync(0xffffffffu, r1, 1));
        r1 = fmaxf(r1, __shfl_xor_sync(0xffffffffu, r1, 2));
        const float nm0 = fmaxf(m0, r0), nm1 = fmaxf(m1, r1);
        const float sc0 = fexp(m0 - nm0), sc1 = fexp(m1 - nm1);
        m0 = nm0; m1 = nm1;

        float ps0 = 0.f, ps1 = 0.f;
#pragma unroll
        for (int nf = 0; nf < 8; ++nf) {
            S[nf][0] = fexp(S[nf][0] - m0);
            S[nf][1] = fexp(S[nf][1] - m0);
            S[nf][2] = fexp(S[nf][2] - m1);
            S[nf][3] = fexp(S[nf][3] - m1);
            ps0 += S[nf][0] + S[nf][1];
            ps1 += S[nf][2] + S[nf][3];
        }
        ps0 += __shfl_xor_sync(0xffffffffu, ps0, 1);
        ps0 += __shfl_xor_sync(0xffffffffu, ps0, 2);
        ps1 += __shfl_xor_sync(0xffffffffu, ps1, 1);
        ps1 += __shfl_xor_sync(0xffffffffu, ps1, 2);
        l0s = l0s * sc0 + ps0;
        l1s = l1s * sc1 + ps1;
#pragma unroll
        for (int nf = 0; nf < 12; ++nf) {
            O[nf][0] *= sc0; O[nf][1] *= sc0;
            O[nf][2] *= sc1; O[nf][3] *= sc1;
        }

        // ---- P fragments (register-to-register, FA2 layout), split hi/lo
        uint32_t PH[4][4], PL[4][4];
#pragma unroll
        for (int ks = 0; ks < 4; ++ks) {
            split2pack(S[2 * ks][0],     S[2 * ks][1],     PH[ks][0], PL[ks][0]);
            split2pack(S[2 * ks][2],     S[2 * ks][3],     PH[ks][1], PL[ks][1]);
            split2pack(S[2 * ks + 1][0], S[2 * ks + 1][1], PH[ks][2], PL[ks][2]);
            split2pack(S[2 * ks + 1][2], S[2 * ks + 1][3], PH[ks][3], PL[ks][3]);
        }

        // ---- O += P V (split-3)
#pragma unroll
        for (int ks = 0; ks < 4; ++ks) {
            uint32_t Vf[12][2];
            const uint32_t vkr = ks * 16 * (FAP * 2) + browV;
#pragma unroll
            for (int nf = 0; nf < 12; ++nf) ldsm2t(Vf[nf], VhS + vkr + nf * 16);
#pragma unroll
            for (int nf = 0; nf < 12; ++nf) mma_bf16(O[nf], PH[ks], Vf[nf]);
#pragma unroll
            for (int nf = 0; nf < 12; ++nf) mma_bf16(O[nf], PL[ks], Vf[nf]);
#pragma unroll
            for (int nf = 0; nf < 12; ++nf) ldsm2t(Vf[nf], VlS + vkr + nf * 16);
#pragma unroll
            for (int nf = 0; nf < 12; ++nf) mma_bf16(O[nf], PH[ks], Vf[nf]);
        }

        __syncthreads();                 // all warps done reading this buffer
        issue(ct + 2, buf);              // refill (wraps to dummy at the end)
    }

    // ---- epilogue: normalize, split, write g_Oh/g_Ol
    const float i0 = 1.f / l0s, i1 = 1.f / l1s;
    size_t rb = ((size_t)b * LSEQ + q0 + wid * 16 + gr) * CH;
#pragma unroll
    for (int nf = 0; nf < 12; ++nf) {
        int col = nf * 8 + c2;
        uint32_t h, l;
        split2pack(O[nf][0] * i0, O[nf][1] * i0, h, l);
        *(uint32_t*)(g_Oh + rb + col) = h;
        *(uint32_t*)(g_Ol + rb + col) = l;
        split2pack(O[nf][2] * i1, O[nf][3] * i1, h, l);
        *(uint32_t*)(g_Oh + rb + 8 * CH + col) = h;
        *(uint32_t*)(g_Ol + rb + 8 * CH + col) = l;
    }
}

// ============================================================================
// Kernel 3: y[b,o,l] = gamma * (Wlast . O) + x via split-bf16 MMA.
// CTA: 128 l x 96 o, K=96 single pass. Epilogue transposed through smem.
// smem: Oh 26624 | Ol 26624 | Wh 19968 | Wl 19968 = 93184; staging reuses Oh/Ol.
// ============================================================================
#define OM_SMEM (2 * 128 * FAP * 2 + 2 * 96 * FAP * 2)

__global__ __launch_bounds__(256, 1) void outmma_kernel(
    const float* __restrict__ x,
    const float* __restrict__ gammap,
    float* __restrict__ out)
{
    extern __shared__ char smraw[];
    const uint32_t base = s2u(smraw);
    const uint32_t OhS = base, OlS = base + 26624, WhS = base + 53248, WlS = base + 73216;
    float* sst = (float*)smraw;          // staging [96 o][132 l], reuses Oh/Ol

    const int l0 = blockIdx.x * 128;
    const int o0 = blockIdx.y * 96;
    const int b  = blockIdx.z;
    const int tid = threadIdx.x, wid = tid >> 5, lane = tid & 31;
    const int wm = wid & 1, wn = wid >> 1;
    const int gr = lane >> 2, c2 = (lane & 3) * 2;
    const float gamma = gammap[0];

    // loads: O tiles (128 rows) + W tiles (96 rows), all bf16 via cp.async
    {
        const __nv_bfloat16* Oh = g_Oh + ((size_t)b * LSEQ + l0) * CH;
        const __nv_bfloat16* Ol = g_Ol + ((size_t)b * LSEQ + l0) * CH;
#pragma unroll
        for (int it = 0; it < 6; ++it) {
            int idx = tid + it * 256;
            int r = idx / 12, c16 = idx % 12;
            cpa16(OhS + r * 208 + c16 * 16, Oh + (size_t)r * CH + c16 * 8);
            cpa16(OlS + r * 208 + c16 * 16, Ol + (size_t)r * CH + c16 * 8);
        }
        const __nv_bfloat16* Wh = g_Wh + (size_t)o0 * CH;
        const __nv_bfloat16* Wl = g_Wl + (size_t)o0 * CH;
#pragma unroll
        for (int it = 0; it < 5; ++it) {
            int idx = tid + it * 256;
            if (idx < 1152) {
                int r = idx / 12, c16 = idx % 12;
                cpa16(WhS + r * 208 + c16 * 16, Wh + (size_t)r * CH + c16 * 8);
                cpa16(WlS + r * 208 + c16 * 16, Wl + (size_t)r * CH + c16 * 8);
            }
        }
        CP_COMMIT();
        CP_WAIT0();
    }
    __syncthreads();

    const uint32_t aoff = ((wm * 64 + (lane & 15)) * FAP + ((lane >> 4) << 3)) * 2;
    const uint32_t bofs = ((wn * 24 + (lane & 7)) * FAP + (((lane >> 3) & 1) << 3)) * 2;

    float D[4][3][4];
#pragma unroll
    for (int mf = 0; mf < 4; ++mf)
#pragma unroll
        for (int nf = 0; nf < 3; ++nf)
#pragma unroll
            for (int e = 0; e < 4; ++e) D[mf][nf][e] = 0.f;

#pragma unroll
    for (int ks = 0; ks < 6; ++ks) {
        uint32_t A[4][4], L[4][4], Bf[3][2];
#pragma unroll
        for (int mf = 0; mf < 4; ++mf)
            ldsm4(A[mf], OhS + aoff + mf * 16 * (FAP * 2) + ks * 32);
#pragma unroll
        for (int nf = 0; nf < 3; ++nf)
            ldsm2(Bf[nf], WhS + bofs + nf * 8 * (FAP * 2) + ks * 32);
#pragma unroll
        for (int mf = 0; mf < 4; ++mf)
#pragma unroll
            for (int nf = 0; nf < 3; ++nf) mma_bf16(D[mf][nf], A[mf], Bf[nf]);
#pragma unroll
        for (int mf = 0; mf < 4; ++mf)
            ldsm4(L[mf], OlS + aoff + mf * 16 * (FAP * 2) + ks * 32);
#pragma unroll
        for (int mf = 0; mf < 4; ++mf)
#pragma unroll
            for (int nf = 0; nf < 3; ++nf) mma_bf16(D[mf][nf], L[mf], Bf[nf]);
#pragma unroll
        for (int nf = 0; nf < 3; ++nf)
            ldsm2(Bf[nf], WlS + bofs + nf * 8 * (FAP * 2) + ks * 32);
#pragma unroll
        for (int mf = 0; mf < 4; ++mf)
#pragma unroll
            for (int nf = 0; nf < 3; ++nf) mma_bf16(D[mf][nf], A[mf], Bf[nf]);
    }
    __syncthreads();   // done reading Oh/Ol; staging may overwrite

    // stage transposed: sst[o][l], pitch 132
#pragma unroll
    for (int mf = 0; mf < 4; ++mf) {
        int row = wm * 64 + mf * 16 + gr;
#pragma unroll
        for (int nf = 0; nf < 3; ++nf) {
            int col = wn * 24 + nf * 8 + c2;
            sst[(col)     * 132 + row]     = D[mf][nf][0];
            sst[(col + 1) * 132 + row]     = D[mf][nf][1];
            sst[(col)     * 132 + row + 8] = D[mf][nf][2];
            sst[(col + 1) * 132 + row + 8] = D[mf][nf][3];
        }
    }
    __syncthreads();

    // coalesced: out[b, o0+o, l0 + 4*l4 ..] = gamma * sst + x
#pragma unroll
    for (int it = 0; it < 12; ++it) {
        int idx = tid + it * 256;
        int o = idx >> 5, l4 = idx & 31;
        float4 v = *(const float4*)&sst[o * 132 + l4 * 4];
        size_t gbase = (size_t)b * COUTC * LSEQ + (size_t)(o0 + o) * LSEQ + l0 + l4 * 4;
        float4 xr = *(const float4*)(x + gbase);
        *(float4*)(out + gbase) = make_float4(fmaf(gamma, v.x, xr.x),
                                              fmaf(gamma, v.y, xr.y),
                                              fmaf(gamma, v.z, xr.z),
                                              fmaf(gamma, v.w, xr.w));
    }
}

// ============================================================================
extern "C" void kernel_launch(void* const* d_in, const int* in_sizes, int n_in,
                              void* d_out, int out_size) {
    const float* x     = (const float*)d_in[0];
    const float* Wq    = (const float*)d_in[1];
    const float* Wk    = (const float*)d_in[2];
    const float* Wv    = (const float*)d_in[3];
    const float* Wl    = (const float*)d_in[4];
    const float* gamma = (const float*)d_in[5];
    float* out = (float*)d_out;

    cudaFuncSetAttribute(projmma_kernel, cudaFuncAttributeMaxDynamicSharedMemorySize, PJ_SMEM);
    cudaFuncSetAttribute(fattn_kernel,   cudaFuncAttributeMaxDynamicSharedMemorySize, FA_SMEM);
    cudaFuncSetAttribute(outmma_kernel,  cudaFuncAttributeMaxDynamicSharedMemorySize, OM_SMEM);

    wsplit_kernel<<<72, 256>>>(Wl);
    projmma_kernel<<<dim3(32, 3, 8), 256, PJ_SMEM>>>(x, Wq, Wk, Wv);
    fattn_kernel<<<dim3(32, 8), 256, FA_SMEM>>>();
    outmma_kernel<<<dim3(32, 8, 8), 256, OM_SMEM>>>(x, gamma, out);
}

// round 8
// speedup vs baseline: 3.3179x; 1.0515x over previous
#include <cuda_runtime.h>
#include <cuda_bf16.h>
#include <cstdint>
#include <cstddef>

#define BB    8
#define CIN   768
#define LSEQ  4096
#define CH    96
#define COUTC 768

// ---- device-global scratch: pre-split bf16 hi/lo pairs ----
__device__ __nv_bfloat16 g_Qh[BB * LSEQ * CH], g_Ql[BB * LSEQ * CH];
__device__ __nv_bfloat16 g_Kh[BB * LSEQ * CH], g_Kl[BB * LSEQ * CH];
__device__ __nv_bfloat16 g_Vh[BB * LSEQ * CH], g_Vl[BB * LSEQ * CH];
__device__ __nv_bfloat16 g_Oh[BB * LSEQ * CH], g_Ol[BB * LSEQ * CH];
__device__ __nv_bfloat16 g_Wh[COUTC * CH],     g_Wl[COUTC * CH];
__device__ __nv_bfloat16 g_Wqh[CH * CIN], g_Wql[CH * CIN];
__device__ __nv_bfloat16 g_Wkh[CH * CIN], g_Wkl[CH * CIN];
__device__ __nv_bfloat16 g_Wvh[CH * CIN], g_Wvl[CH * CIN];

// ============================================================================
// PTX helpers
// ============================================================================
__device__ __forceinline__ uint32_t s2u(const void* p) {
    return (uint32_t)__cvta_generic_to_shared(p);
}
__device__ __forceinline__ void ldsm4(uint32_t r[4], uint32_t a) {
    asm volatile("ldmatrix.sync.aligned.m8n8.x4.shared.b16 {%0,%1,%2,%3}, [%4];"
                 : "=r"(r[0]), "=r"(r[1]), "=r"(r[2]), "=r"(r[3]) : "r"(a));
}
__device__ __forceinline__ void ldsm4t(uint32_t r[4], uint32_t a) {
    asm volatile("ldmatrix.sync.aligned.m8n8.x4.trans.shared.b16 {%0,%1,%2,%3}, [%4];"
                 : "=r"(r[0]), "=r"(r[1]), "=r"(r[2]), "=r"(r[3]) : "r"(a));
}
__device__ __forceinline__ void ldsm2(uint32_t r[2], uint32_t a) {
    asm volatile("ldmatrix.sync.aligned.m8n8.x2.shared.b16 {%0,%1}, [%2];"
                 : "=r"(r[0]), "=r"(r[1]) : "r"(a));
}
__device__ __forceinline__ void mma_bf16(float d[4], const uint32_t a[4], const uint32_t b[2]) {
    asm volatile("mma.sync.aligned.m16n8k16.row.col.f32.bf16.bf16.f32 "
                 "{%0,%1,%2,%3}, {%4,%5,%6,%7}, {%8,%9}, {%0,%1,%2,%3};"
                 : "+f"(d[0]), "+f"(d[1]), "+f"(d[2]), "+f"(d[3])
                 : "r"(a[0]), "r"(a[1]), "r"(a[2]), "r"(a[3]), "r"(b[0]), "r"(b[1]));
}
__device__ __forceinline__ void cpa16(uint32_t dst, const void* src) {
    asm volatile("cp.async.cg.shared.global [%0], [%1], 16;" :: "r"(dst), "l"(src));
}
#define CP_COMMIT() asm volatile("cp.async.commit_group;" ::: "memory")
#define CP_WAIT0()  asm volatile("cp.async.wait_group 0;" ::: "memory")
#define CP_WAIT1()  asm volatile("cp.async.wait_group 1;" ::: "memory")

__device__ __forceinline__ void split4(__nv_bfloat16* hiB, __nv_bfloat16* loB,
                                       int eoff, float4 v) {
    float f[4] = {v.x, v.y, v.z, v.w};
    unsigned short h[4], l[4];
#pragma unroll
    for (int i = 0; i < 4; ++i) {
        __nv_bfloat16 hb = __float2bfloat16(f[i]);
        float r = f[i] - __bfloat162float(hb);
        h[i] = __bfloat16_as_ushort(hb);
        l[i] = __bfloat16_as_ushort(__float2bfloat16(r));
    }
    *(uint2*)(hiB + eoff) = make_uint2((uint32_t)h[0] | ((uint32_t)h[1] << 16),
                                       (uint32_t)h[2] | ((uint32_t)h[3] << 16));
    *(uint2*)(loB + eoff) = make_uint2((uint32_t)l[0] | ((uint32_t)l[1] << 16),
                                       (uint32_t)l[2] | ((uint32_t)l[3] << 16));
}
__device__ __forceinline__ void split2pack(float a, float b, uint32_t& hi, uint32_t& lo) {
    __nv_bfloat16 ah = __float2bfloat16(a), bh = __float2bfloat16(b);
    float ar = a - __bfloat162float(ah);
    float br = b - __bfloat162float(bh);
    hi = (uint32_t)__bfloat16_as_ushort(ah) | ((uint32_t)__bfloat16_as_ushort(bh) << 16);
    lo = (uint32_t)__bfloat16_as_ushort(__float2bfloat16(ar)) |
         ((uint32_t)__bfloat16_as_ushort(__float2bfloat16(br)) << 16);
}
__device__ __forceinline__ float fexp(float x) {
    float y = x * 1.4426950408889634f;
    y = fmaxf(y, -126.0f);
    float t = y + 12582912.0f;
    float f = y - (t - 12582912.0f);
    float p =            1.3333558146e-3f;
    p = fmaf(p, f, 9.6181291076e-3f);
    p = fmaf(p, f, 5.5504108664e-2f);
    p = fmaf(p, f, 2.4022650696e-1f);
    p = fmaf(p, f, 6.9314718056e-1f);
    p = fmaf(p, f, 1.0f);
    int e = (__float_as_int(t) - 0x4b400000 + 127) << 23;
    return p * __int_as_float(e);
}

// ============================================================================
// Kernel 0: split all 4 weight matrices into bf16 hi/lo.
// 4 x 73728 elems = 73728 float4 total. grid 288 x 256.
// ============================================================================
__global__ __launch_bounds__(256) void wsplit_kernel(
    const float* __restrict__ Wq, const float* __restrict__ Wk,
    const float* __restrict__ Wv, const float* __restrict__ Wlast)
{
    int g = blockIdx.x * 256 + threadIdx.x;
    int m = g / 18432, idx = g % 18432;
    const float* src = (m == 0) ? Wq : (m == 1) ? Wk : (m == 2) ? Wv : Wlast;
    __nv_bfloat16 *dh, *dl;
    if (m == 0)      { dh = g_Wqh; dl = g_Wql; }
    else if (m == 1) { dh = g_Wkh; dl = g_Wkl; }
    else if (m == 2) { dh = g_Wvh; dl = g_Wvl; }
    else             { dh = g_Wh;  dl = g_Wl;  }
    float4 v = *(const float4*)(src + idx * 4);
    split4(dh, dl, idx * 4, v);
}

// ============================================================================
// Kernel 1: fused QKV projection. One CTA computes Q,K,V for 128 l-rows:
// x chunk staged/split once, reused for all 3 outputs. W pre-split, cp.async.
// 8 warps = 2(l) x 4(o); warp tile 64l x 24o per output.
// smem: Xh,Xl 2x17408 | 6 W tiles (Wqh,Wql,Wkh,Wkl,Wvh,Wvl) x 13824 = 152576
// ============================================================================
#define XP 136
#define WROW 144                      // W smem row pitch bytes (72 bf16)
#define WTILE (96 * WROW)             // 13824
#define PJ_WBASE (2 * 64 * XP * 2)    // 34816
#define PJ_SMEM (PJ_WBASE + 6 * WTILE)

__global__ __launch_bounds__(256, 1) void projmma_kernel(const float* __restrict__ x) {
    extern __shared__ char smraw[];
    __nv_bfloat16* Xh = (__nv_bfloat16*)smraw;
    __nv_bfloat16* Xl = Xh + 64 * XP;
    const uint32_t base = s2u(smraw);
    const uint32_t XhS = base, XlS = base + 17408, WB = base + PJ_WBASE;

    const int l0 = blockIdx.x * 128;
    const int b  = blockIdx.z;
    const int tid = threadIdx.x, wid = tid >> 5, lane = tid & 31;
    const int wm = wid & 1, wn = wid >> 1;

    const int gr = lane >> 2, c2 = (lane & 3) * 2;
    const uint32_t kla = (lane & 7) + ((lane >> 4) << 3);
    const uint32_t mla = ((lane >> 3) & 1) * 8 + wm * 64;
    const uint32_t bofs = ((wn * 24 + (lane & 7)) * 72 + (((lane >> 3) & 1) << 3)) * 2;

    const __nv_bfloat16* Wsrc[6] = {g_Wqh, g_Wql, g_Wkh, g_Wkl, g_Wvh, g_Wvl};

    float D[3][4][3][4];
#pragma unroll
    for (int w = 0; w < 3; ++w)
#pragma unroll
        for (int mf = 0; mf < 4; ++mf)
#pragma unroll
            for (int nf = 0; nf < 3; ++nf)
#pragma unroll
                for (int e = 0; e < 4; ++e) D[w][mf][nf][e] = 0.f;

    const float* xb = x + (size_t)b * CIN * LSEQ + l0;

    for (int c0 = 0; c0 < CIN; c0 += 64) {
        __syncthreads();
        // W tiles via cp.async (issue first; overlaps x conversion below)
#pragma unroll
        for (int it = 0; it < 18; ++it) {
            int idx = tid + it * 256;
            int t = idx / 768, r = idx % 768;
            int o = r >> 3, c16 = r & 7;
            cpa16(WB + t * WTILE + o * WROW + c16 * 16,
                  Wsrc[t] + (size_t)o * CIN + c0 + c16 * 8);
        }
        CP_COMMIT();
        // x chunk [64 c][128 l] -> split bf16 (shared by Q,K,V)
#pragma unroll
        for (int it = 0; it < 8; ++it) {
            int idx = tid + it * 256;
            int c = idx >> 5, l4 = idx & 31;
            float4 v = *(const float4*)(xb + (size_t)(c0 + c) * LSEQ + l4 * 4);
            split4(Xh, Xl, c * XP + l4 * 4, v);
        }
        CP_WAIT0();
        __syncthreads();

#pragma unroll
        for (int ks = 0; ks < 4; ++ks) {
            uint32_t A[4][4], L[4][4];
            const uint32_t arow = (ks * 16 + kla) * XP;
#pragma unroll
            for (int mf = 0; mf < 4; ++mf) {
                ldsm4t(A[mf], XhS + (arow + mla + mf * 16) * 2);
                ldsm4t(L[mf], XlS + (arow + mla + mf * 16) * 2);
            }
#pragma unroll
            for (int w = 0; w < 3; ++w) {
                const uint32_t whS = WB + (w * 2) * WTILE;
                const uint32_t wlS = whS + WTILE;
                uint32_t Bf[3][2];
#pragma unroll
                for (int nf = 0; nf < 3; ++nf)
                    ldsm2(Bf[nf], whS + bofs + nf * 8 * WROW + ks * 32);
#pragma unroll
                for (int mf = 0; mf < 4; ++mf)
#pragma unroll
                    for (int nf = 0; nf < 3; ++nf) mma_bf16(D[w][mf][nf], A[mf], Bf[nf]);
#pragma unroll
                for (int mf = 0; mf < 4; ++mf)
#pragma unroll
                    for (int nf = 0; nf < 3; ++nf) mma_bf16(D[w][mf][nf], L[mf], Bf[nf]);
#pragma unroll
                for (int nf = 0; nf < 3; ++nf)
                    ldsm2(Bf[nf], wlS + bofs + nf * 8 * WROW + ks * 32);
#pragma unroll
                for (int mf = 0; mf < 4; ++mf)
#pragma unroll
                    for (int nf = 0; nf < 3; ++nf) mma_bf16(D[w][mf][nf], A[mf], Bf[nf]);
            }
        }
    }

    __nv_bfloat16* OH[3] = {g_Qh, g_Kh, g_Vh};
    __nv_bfloat16* OL[3] = {g_Ql, g_Kl, g_Vl};
#pragma unroll
    for (int w = 0; w < 3; ++w) {
#pragma unroll
        for (int mf = 0; mf < 4; ++mf) {
            int row = wm * 64 + mf * 16 + gr;
            size_t rb = ((size_t)b * LSEQ + l0 + row) * CH;
#pragma unroll
            for (int nf = 0; nf < 3; ++nf) {
                int col = wn * 24 + nf * 8 + c2;
                uint32_t h, l;
                split2pack(D[w][mf][nf][0], D[w][mf][nf][1], h, l);
                *(uint32_t*)(OH[w] + rb + col) = h;
                *(uint32_t*)(OL[w] + rb + col) = l;
                split2pack(D[w][mf][nf][2], D[w][mf][nf][3], h, l);
                *(uint32_t*)(OH[w] + rb + 8 * CH + col) = h;
                *(uint32_t*)(OL[w] + rb + 8 * CH + col) = l;
            }
        }
    }
}

// ============================================================================
// Kernel 2: fused flash attention. 128-key chunks, double-buffered cp.async,
// wide ldsm4/ldsm4t. CTA: 128 q, 8 warps x 16 q.
// smem: 2 buffers x {Kh,Kl,Vh,Vl} x (128 x 104 bf16) = 212992 B
// ============================================================================
#define FAP 104
#define TPB (128 * FAP * 2)           // 26624 per tile
#define FA_SMEM (2 * 4 * TPB)         // 212992

__global__ __launch_bounds__(256, 1) void fattn_kernel() {
    extern __shared__ char smraw[];
    const uint32_t base = s2u(smraw);
    const int tid = threadIdx.x, wid = tid >> 5, lane = tid & 31;
    const int b = blockIdx.y, q0 = blockIdx.x * 128;
    const int gr = lane >> 2, c2 = (lane & 3) * 2;

    // ---- stage Q hi/lo into buf0 tiles 0/1, build persistent fragments
    {
        const __nv_bfloat16* Qh = g_Qh + ((size_t)b * LSEQ + q0) * CH;
        const __nv_bfloat16* Ql = g_Ql + ((size_t)b * LSEQ + q0) * CH;
#pragma unroll
        for (int it = 0; it < 6; ++it) {
            int idx = tid + it * 256;
            int r = idx / 12, c16 = idx % 12;
            cpa16(base + r * 208 + c16 * 16, Qh + (size_t)r * CH + c16 * 8);
            cpa16(base + TPB + r * 208 + c16 * 16, Ql + (size_t)r * CH + c16 * 8);
        }
        CP_COMMIT();
        CP_WAIT0();
    }
    __syncthreads();

    uint32_t QH[6][4], QL[6][4];
    {
        const uint32_t arow = ((wid * 16 + (lane & 15)) * FAP + ((lane >> 4) << 3)) * 2;
#pragma unroll
        for (int ks = 0; ks < 6; ++ks) {
            ldsm4(QH[ks], base + arow + ks * 32);
            ldsm4(QL[ks], base + TPB + arow + ks * 32);
        }
    }
    __syncthreads();

    float O[12][4];
#pragma unroll
    for (int nf = 0; nf < 12; ++nf)
#pragma unroll
        for (int e = 0; e < 4; ++e) O[nf][e] = 0.f;
    float m0 = -1e30f, m1 = -1e30f, l0s = 0.f, l1s = 0.f;

    const __nv_bfloat16* srcs[4] = {
        g_Kh + (size_t)b * LSEQ * CH, g_Kl + (size_t)b * LSEQ * CH,
        g_Vh + (size_t)b * LSEQ * CH, g_Vl + (size_t)b * LSEQ * CH };

    // wide-B lane addressing
    const uint32_t bofsK4 = (lane & 7) * 208 + ((lane >> 3) & 1) * 16 + (lane >> 4) * 8 * 208;
    const uint32_t browV4 = (lane & 15) * 208 + (lane >> 4) * 16;

    auto issue = [&](int ct, uint32_t bufbase) {
        const int k0 = (ct & 31) * 128;
#pragma unroll
        for (int it = 0; it < 24; ++it) {
            int idx = tid + it * 256;
            int tile = idx / 1536, w = idx % 1536;
            int r = w / 12, c16 = w % 12;
            cpa16(bufbase + tile * TPB + r * 208 + c16 * 16,
                  srcs[tile] + (size_t)(k0 + r) * CH + c16 * 8);
        }
        CP_COMMIT();
    };

    issue(0, base);
    issue(1, base + 4 * TPB);

    for (int ct = 0; ct < 32; ++ct) {
        const uint32_t buf = base + (ct & 1) * (4 * TPB);
        CP_WAIT1();
        __syncthreads();

        const uint32_t KhS = buf, KlS = buf + TPB, VhS = buf + 2 * TPB, VlS = buf + 3 * TPB;

        // ---- S = Q K^T (split-3), warp tile 16 x 128
        float S[16][4];
#pragma unroll
        for (int nf = 0; nf < 16; ++nf)
#pragma unroll
            for (int e = 0; e < 4; ++e) S[nf][e] = 0.f;

#pragma unroll
        for (int ks = 0; ks < 6; ++ks) {
            uint32_t Bf[16][2];
#pragma unroll
            for (int p = 0; p < 8; ++p) {
                uint32_t r4[4];
                ldsm4(r4, KhS + bofsK4 + p * 16 * 208 + ks * 32);
                Bf[2 * p][0] = r4[0]; Bf[2 * p][1] = r4[1];
                Bf[2 * p + 1][0] = r4[2]; Bf[2 * p + 1][1] = r4[3];
            }
#pragma unroll
            for (int nf = 0; nf < 16; ++nf) mma_bf16(S[nf], QH[ks], Bf[nf]);
#pragma unroll
            for (int nf = 0; nf < 16; ++nf) mma_bf16(S[nf], QL[ks], Bf[nf]);
#pragma unroll
            for (int p = 0; p < 8; ++p) {
                uint32_t r4[4];
                ldsm4(r4, KlS + bofsK4 + p * 16 * 208 + ks * 32);
                Bf[2 * p][0] = r4[0]; Bf[2 * p][1] = r4[1];
                Bf[2 * p + 1][0] = r4[2]; Bf[2 * p + 1][1] = r4[3];
            }
#pragma unroll
            for (int nf = 0; nf < 16; ++nf) mma_bf16(S[nf], QH[ks], Bf[nf]);
        }

        // ---- online softmax (rows gr and gr+8)
        float r0 = -1e30f, r1 = -1e30f;
#pragma unroll
        for (int nf = 0; nf < 16; ++nf) {
            r0 = fmaxf(r0, fmaxf(S[nf][0], S[nf][1]));
            r1 = fmaxf(r1, fmaxf(S[nf][2], S[nf][3]));
        }
        r0 = fmaxf(r0, __shfl_xor_sync(0xffffffffu, r0, 1));
        r0 = fmaxf(r0, __shfl_xor_sync(0xffffffffu, r0, 2));
        r1 = fmaxf(r1, __shfl_xor_sync(0xffffffffu, r1, 1));
        r1 = fmaxf(r1, __shfl_xor_sync(0xffffffffu, r1, 2));
        const float nm0 = fmaxf(m0, r0), nm1 = fmaxf(m1, r1);
        const float sc0 = fexp(m0 - nm0), sc1 = fexp(m1 - nm1);
        m0 = nm0; m1 = nm1;

        float ps0 = 0.f, ps1 = 0.f;
#pragma unroll
        for (int nf = 0; nf < 16; ++nf) {
            S[nf][0] = fexp(S[nf][0] - m0);
            S[nf][1] = fexp(S[nf][1] - m0);
            S[nf][2] = fexp(S[nf][2] - m1);
            S[nf][3] = fexp(S[nf][3] - m1);
            ps0 += S[nf][0] + S[nf][1];
            ps1 += S[nf][2] + S[nf][3];
        }
        ps0 += __shfl_xor_sync(0xffffffffu, ps0, 1);
        ps0 += __shfl_xor_sync(0xffffffffu, ps0, 2);
        ps1 += __shfl_xor_sync(0xffffffffu, ps1, 1);
        ps1 += __shfl_xor_sync(0xffffffffu, ps1, 2);
        l0s = l0s * sc0 + ps0;
        l1s = l1s * sc1 + ps1;
#pragma unroll
        for (int nf = 0; nf < 12; ++nf) {
            O[nf][0] *= sc0; O[nf][1] *= sc0;
            O[nf][2] *= sc1; O[nf][3] *= sc1;
        }

        // ---- O += P V (split-3): per 16-key step, pack P then wide-V loads
#pragma unroll
        for (int ks = 0; ks < 8; ++ks) {
            uint32_t PH[4], PL[4];
            split2pack(S[2 * ks][0],     S[2 * ks][1],     PH[0], PL[0]);
            split2pack(S[2 * ks][2],     S[2 * ks][3],     PH[1], PL[1]);
            split2pack(S[2 * ks + 1][0], S[2 * ks + 1][1], PH[2], PL[2]);
            split2pack(S[2 * ks + 1][2], S[2 * ks + 1][3], PH[3], PL[3]);

            uint32_t Vf[12][2];
            const uint32_t vkr = ks * 16 * 208 + browV4;
#pragma unroll
            for (int p = 0; p < 6; ++p) {
                uint32_t r4[4];
                ldsm4t(r4, VhS + vkr + p * 32);
                Vf[2 * p][0] = r4[0]; Vf[2 * p][1] = r4[1];
                Vf[2 * p + 1][0] = r4[2]; Vf[2 * p + 1][1] = r4[3];
            }
#pragma unroll
            for (int nf = 0; nf < 12; ++nf) mma_bf16(O[nf], PH, Vf[nf]);
#pragma unroll
            for (int nf = 0; nf < 12; ++nf) mma_bf16(O[nf], PL, Vf[nf]);
#pragma unroll
            for (int p = 0; p < 6; ++p) {
                uint32_t r4[4];
                ldsm4t(r4, VlS + vkr + p * 32);
                Vf[2 * p][0] = r4[0]; Vf[2 * p][1] = r4[1];
                Vf[2 * p + 1][0] = r4[2]; Vf[2 * p + 1][1] = r4[3];
            }
#pragma unroll
            for (int nf = 0; nf < 12; ++nf) mma_bf16(O[nf], PH, Vf[nf]);
        }

        __syncthreads();
        issue(ct + 2, buf);
    }

    // ---- epilogue: normalize, split, write g_Oh/g_Ol
    const float i0 = 1.f / l0s, i1 = 1.f / l1s;
    size_t rb = ((size_t)b * LSEQ + q0 + wid * 16 + gr) * CH;
#pragma unroll
    for (int nf = 0; nf < 12; ++nf) {
        int col = nf * 8 + c2;
        uint32_t h, l;
        split2pack(O[nf][0] * i0, O[nf][1] * i0, h, l);
        *(uint32_t*)(g_Oh + rb + col) = h;
        *(uint32_t*)(g_Ol + rb + col) = l;
        split2pack(O[nf][2] * i1, O[nf][3] * i1, h, l);
        *(uint32_t*)(g_Oh + rb + 8 * CH + col) = h;
        *(uint32_t*)(g_Ol + rb + 8 * CH + col) = l;
    }
}

// ============================================================================
// Kernel 3: y[b,o,l] = gamma * (Wlast . O) + x via split-bf16 MMA.
// reg-capped for 2 CTAs/SM (latency-bound kernel).
// ============================================================================
#define OM_SMEM (2 * 128 * FAP * 2 + 2 * 96 * FAP * 2)

__global__ __launch_bounds__(256, 2) void outmma_kernel(
    const float* __restrict__ x,
    const float* __restrict__ gammap,
    float* __restrict__ out)
{
    extern __shared__ char smraw[];
    const uint32_t base = s2u(smraw);
    const uint32_t OhS = base, OlS = base + 26624, WhS = base + 53248, WlS = base + 73216;
    float* sst = (float*)smraw;

    const int l0 = blockIdx.x * 128;
    const int o0 = blockIdx.y * 96;
    const int b  = blockIdx.z;
    const int tid = threadIdx.x, wid = tid >> 5, lane = tid & 31;
    const int wm = wid & 1, wn = wid >> 1;
    const int gr = lane >> 2, c2 = (lane & 3) * 2;
    const float gamma = gammap[0];

    {
        const __nv_bfloat16* Oh = g_Oh + ((size_t)b * LSEQ + l0) * CH;
        const __nv_bfloat16* Ol = g_Ol + ((size_t)b * LSEQ + l0) * CH;
#pragma unroll
        for (int it = 0; it < 6; ++it) {
            int idx = tid + it * 256;
            int r = idx / 12, c16 = idx % 12;
            cpa16(OhS + r * 208 + c16 * 16, Oh + (size_t)r * CH + c16 * 8);
            cpa16(OlS + r * 208 + c16 * 16, Ol + (size_t)r * CH + c16 * 8);
        }
        const __nv_bfloat16* Wh = g_Wh + (size_t)o0 * CH;
        const __nv_bfloat16* Wl = g_Wl + (size_t)o0 * CH;
#pragma unroll
        for (int it = 0; it < 5; ++it) {
            int idx = tid + it * 256;
            if (idx < 1152) {
                int r = idx / 12, c16 = idx % 12;
                cpa16(WhS + r * 208 + c16 * 16, Wh + (size_t)r * CH + c16 * 8);
                cpa16(WlS + r * 208 + c16 * 16, Wl + (size_t)r * CH + c16 * 8);
            }
        }
        CP_COMMIT();
        CP_WAIT0();
    }
    __syncthreads();

    const uint32_t aoff = ((wm * 64 + (lane & 15)) * FAP + ((lane >> 4) << 3)) * 2;
    const uint32_t bofs = ((wn * 24 + (lane & 7)) * FAP + (((lane >> 3) & 1) << 3)) * 2;

    float D[4][3][4];
#pragma unroll
    for (int mf = 0; mf < 4; ++mf)
#pragma unroll
        for (int nf = 0; nf < 3; ++nf)
#pragma unroll
            for (int e = 0; e < 4; ++e) D[mf][nf][e] = 0.f;

#pragma unroll
    for (int ks = 0; ks < 6; ++ks) {
        uint32_t A[4][4], L[4][4], Bf[3][2];
#pragma unroll
        for (int mf = 0; mf < 4; ++mf)
            ldsm4(A[mf], OhS + aoff + mf * 16 * (FAP * 2) + ks * 32);
#pragma unroll
        for (int nf = 0; nf < 3; ++nf)
            ldsm2(Bf[nf], WhS + bofs + nf * 8 * (FAP * 2) + ks * 32);
#pragma unroll
        for (int mf = 0; mf < 4; ++mf)
#pragma unroll
            for (int nf = 0; nf < 3; ++nf) mma_bf16(D[mf][nf], A[mf], Bf[nf]);
#pragma unroll
        for (int mf = 0; mf < 4; ++mf)
            ldsm4(L[mf], OlS + aoff + mf * 16 * (FAP * 2) + ks * 32);
#pragma unroll
        for (int mf = 0; mf < 4; ++mf)
#pragma unroll
            for (int nf = 0; nf < 3; ++nf) mma_bf16(D[mf][nf], L[mf], Bf[nf]);
#pragma unroll
        for (int nf = 0; nf < 3; ++nf)
            ldsm2(Bf[nf], WlS + bofs + nf * 8 * (FAP * 2) + ks * 32);
#pragma unroll
        for (int mf = 0; mf < 4; ++mf)
#pragma unroll
            for (int nf = 0; nf < 3; ++nf) mma_bf16(D[mf][nf], A[mf], Bf[nf]);
    }
    __syncthreads();

#pragma unroll
    for (int mf = 0; mf < 4; ++mf) {
        int row = wm * 64 + mf * 16 + gr;
#pragma unroll
        for (int nf = 0; nf < 3; ++nf) {
            int col = wn * 24 + nf * 8 + c2;
            sst[(col)     * 132 + row]     = D[mf][nf][0];
            sst[(col + 1) * 132 + row]     = D[mf][nf][1];
            sst[(col)     * 132 + row + 8] = D[mf][nf][2];
            sst[(col + 1) * 132 + row + 8] = D[mf][nf][3];
        }
    }
    __syncthreads();

#pragma unroll
    for (int it = 0; it < 12; ++it) {
        int idx = tid + it * 256;
        int o = idx >> 5, l4 = idx & 31;
        float4 v = *(const float4*)&sst[o * 132 + l4 * 4];
        size_t gbase = (size_t)b * COUTC * LSEQ + (size_t)(o0 + o) * LSEQ + l0 + l4 * 4;
        float4 xr = *(const float4*)(x + gbase);
        *(float4*)(out + gbase) = make_float4(fmaf(gamma, v.x, xr.x),
                                              fmaf(gamma, v.y, xr.y),
                                              fmaf(gamma, v.z, xr.z),
                                              fmaf(gamma, v.w, xr.w));
    }
}

// ============================================================================
extern "C" void kernel_launch(void* const* d_in, const int* in_sizes, int n_in,
                              void* d_out, int out_size) {
    const float* x     = (const float*)d_in[0];
    const float* Wq    = (const float*)d_in[1];
    const float* Wk    = (const float*)d_in[2];
    const float* Wv    = (const float*)d_in[3];
    const float* Wl    = (const float*)d_in[4];
    const float* gamma = (const float*)d_in[5];
    float* out = (float*)d_out;

    cudaFuncSetAttribute(projmma_kernel, cudaFuncAttributeMaxDynamicSharedMemorySize, PJ_SMEM);
    cudaFuncSetAttribute(fattn_kernel,   cudaFuncAttributeMaxDynamicSharedMemorySize, FA_SMEM);
    cudaFuncSetAttribute(outmma_kernel,  cudaFuncAttributeMaxDynamicSharedMemorySize, OM_SMEM);

    wsplit_kernel<<<288, 256>>>(Wq, Wk, Wv, Wl);
    projmma_kernel<<<dim3(32, 1, 8), 256, PJ_SMEM>>>(x);
    fattn_kernel<<<dim3(32, 8), 256, FA_SMEM>>>();
    outmma_kernel<<<dim3(32, 8, 8), 256, OM_SMEM>>>(x, gamma, out);
}

// round 11
// speedup vs baseline: 3.3726x; 1.0165x over previous
#include <cuda_runtime.h>
#include <cuda_bf16.h>
#include <cstdint>
#include <cstddef>

#define BB    8
#define CIN   768
#define LSEQ  4096
#define CH    96
#define COUTC 768

// ---- device-global scratch: pre-split bf16 hi/lo pairs ----
__device__ __nv_bfloat16 g_Qh[BB * LSEQ * CH], g_Ql[BB * LSEQ * CH];
__device__ __nv_bfloat16 g_Kh[BB * LSEQ * CH], g_Kl[BB * LSEQ * CH];
__device__ __nv_bfloat16 g_Vh[BB * LSEQ * CH], g_Vl[BB * LSEQ * CH];
__device__ __nv_bfloat16 g_Oh[BB * LSEQ * CH], g_Ol[BB * LSEQ * CH];
__device__ __nv_bfloat16 g_Wh[COUTC * CH],     g_Wl[COUTC * CH];
__device__ __nv_bfloat16 g_Wqh[CH * CIN], g_Wql[CH * CIN];
__device__ __nv_bfloat16 g_Wkh[CH * CIN], g_Wkl[CH * CIN];
__device__ __nv_bfloat16 g_Wvh[CH * CIN], g_Wvl[CH * CIN];

// ============================================================================
// PTX helpers
// ============================================================================
__device__ __forceinline__ uint32_t s2u(const void* p) {
    return (uint32_t)__cvta_generic_to_shared(p);
}
__device__ __forceinline__ void ldsm4(uint32_t r[4], uint32_t a) {
    asm volatile("ldmatrix.sync.aligned.m8n8.x4.shared.b16 {%0,%1,%2,%3}, [%4];"
                 : "=r"(r[0]), "=r"(r[1]), "=r"(r[2]), "=r"(r[3]) : "r"(a));
}
__device__ __forceinline__ void ldsm4t(uint32_t r[4], uint32_t a) {
    asm volatile("ldmatrix.sync.aligned.m8n8.x4.trans.shared.b16 {%0,%1,%2,%3}, [%4];"
                 : "=r"(r[0]), "=r"(r[1]), "=r"(r[2]), "=r"(r[3]) : "r"(a));
}
__device__ __forceinline__ void ldsm2(uint32_t r[2], uint32_t a) {
    asm volatile("ldmatrix.sync.aligned.m8n8.x2.shared.b16 {%0,%1}, [%2];"
                 : "=r"(r[0]), "=r"(r[1]) : "r"(a));
}
__device__ __forceinline__ void mma_bf16(float d[4], const uint32_t a[4], const uint32_t b[2]) {
    asm volatile("mma.sync.aligned.m16n8k16.row.col.f32.bf16.bf16.f32 "
                 "{%0,%1,%2,%3}, {%4,%5,%6,%7}, {%8,%9}, {%0,%1,%2,%3};"
                 : "+f"(d[0]), "+f"(d[1]), "+f"(d[2]), "+f"(d[3])
                 : "r"(a[0]), "r"(a[1]), "r"(a[2]), "r"(a[3]), "r"(b[0]), "r"(b[1]));
}
__device__ __forceinline__ void cpa16(uint32_t dst, const void* src) {
    asm volatile("cp.async.cg.shared.global [%0], [%1], 16;" :: "r"(dst), "l"(src));
}
#define CP_COMMIT() asm volatile("cp.async.commit_group;" ::: "memory")
#define CP_WAIT0()  asm volatile("cp.async.wait_group 0;" ::: "memory")
#define CP_WAIT1()  asm volatile("cp.async.wait_group 1;" ::: "memory")

__device__ __forceinline__ void split4(__nv_bfloat16* hiB, __nv_bfloat16* loB,
                                       int eoff, float4 v) {
    float f[4] = {v.x, v.y, v.z, v.w};
    unsigned short h[4], l[4];
#pragma unroll
    for (int i = 0; i < 4; ++i) {
        __nv_bfloat16 hb = __float2bfloat16(f[i]);
        float r = f[i] - __bfloat162float(hb);
        h[i] = __bfloat16_as_ushort(hb);
        l[i] = __bfloat16_as_ushort(__float2bfloat16(r));
    }
    *(uint2*)(hiB + eoff) = make_uint2((uint32_t)h[0] | ((uint32_t)h[1] << 16),
                                       (uint32_t)h[2] | ((uint32_t)h[3] << 16));
    *(uint2*)(loB + eoff) = make_uint2((uint32_t)l[0] | ((uint32_t)l[1] << 16),
                                       (uint32_t)l[2] | ((uint32_t)l[3] << 16));
}
__device__ __forceinline__ void split2pack(float a, float b, uint32_t& hi, uint32_t& lo) {
    __nv_bfloat16 ah = __float2bfloat16(a), bh = __float2bfloat16(b);
    float ar = a - __bfloat162float(ah);
    float br = b - __bfloat162float(bh);
    hi = (uint32_t)__bfloat16_as_ushort(ah) | ((uint32_t)__bfloat16_as_ushort(bh) << 16);
    lo = (uint32_t)__bfloat16_as_ushort(__float2bfloat16(ar)) |
         ((uint32_t)__bfloat16_as_ushort(__float2bfloat16(br)) << 16);
}
__device__ __forceinline__ float fexp(float x) {
    float y = x * 1.4426950408889634f;
    y = fmaxf(y, -126.0f);
    float t = y + 12582912.0f;
    float f = y - (t - 12582912.0f);
    float p =            1.3333558146e-3f;
    p = fmaf(p, f, 9.6181291076e-3f);
    p = fmaf(p, f, 5.5504108664e-2f);
    p = fmaf(p, f, 2.4022650696e-1f);
    p = fmaf(p, f, 6.9314718056e-1f);
    p = fmaf(p, f, 1.0f);
    int e = (__float_as_int(t) - 0x4b400000 + 127) << 23;
    return p * __int_as_float(e);
}

// ============================================================================
// Kernel 0: split all 4 weight matrices into bf16 hi/lo.
// ============================================================================
__global__ __launch_bounds__(256) void wsplit_kernel(
    const float* __restrict__ Wq, const float* __restrict__ Wk,
    const float* __restrict__ Wv, const float* __restrict__ Wlast)
{
    int g = blockIdx.x * 256 + threadIdx.x;
    int m = g / 18432, idx = g % 18432;
    const float* src = (m == 0) ? Wq : (m == 1) ? Wk : (m == 2) ? Wv : Wlast;
    __nv_bfloat16 *dh, *dl;
    if (m == 0)      { dh = g_Wqh; dl = g_Wql; }
    else if (m == 1) { dh = g_Wkh; dl = g_Wkl; }
    else if (m == 2) { dh = g_Wvh; dl = g_Wvl; }
    else             { dh = g_Wh;  dl = g_Wl;  }
    float4 v = *(const float4*)(src + idx * 4);
    split4(dh, dl, idx * 4, v);
}

// ============================================================================
// Kernel 1: fused QKV projection (unchanged from R7 pass).
// ============================================================================
#define XP 136
#define WROW 144
#define WTILE (96 * WROW)
#define PJ_WBASE (2 * 64 * XP * 2)
#define PJ_SMEM (PJ_WBASE + 6 * WTILE)

__global__ __launch_bounds__(256, 1) void projmma_kernel(const float* __restrict__ x) {
    extern __shared__ char smraw[];
    __nv_bfloat16* Xh = (__nv_bfloat16*)smraw;
    __nv_bfloat16* Xl = Xh + 64 * XP;
    const uint32_t base = s2u(smraw);
    const uint32_t XhS = base, XlS = base + 17408, WB = base + PJ_WBASE;

    const int l0 = blockIdx.x * 128;
    const int b  = blockIdx.z;
    const int tid = threadIdx.x, wid = tid >> 5, lane = tid & 31;
    const int wm = wid & 1, wn = wid >> 1;

    const int gr = lane >> 2, c2 = (lane & 3) * 2;
    const uint32_t kla = (lane & 7) + ((lane >> 4) << 3);
    const uint32_t mla = ((lane >> 3) & 1) * 8 + wm * 64;
    const uint32_t bofs = ((wn * 24 + (lane & 7)) * 72 + (((lane >> 3) & 1) << 3)) * 2;

    const __nv_bfloat16* Wsrc[6] = {g_Wqh, g_Wql, g_Wkh, g_Wkl, g_Wvh, g_Wvl};

    float D[3][4][3][4];
#pragma unroll
    for (int w = 0; w < 3; ++w)
#pragma unroll
        for (int mf = 0; mf < 4; ++mf)
#pragma unroll
            for (int nf = 0; nf < 3; ++nf)
#pragma unroll
                for (int e = 0; e < 4; ++e) D[w][mf][nf][e] = 0.f;

    const float* xb = x + (size_t)b * CIN * LSEQ + l0;

    for (int c0 = 0; c0 < CIN; c0 += 64) {
        __syncthreads();
#pragma unroll
        for (int it = 0; it < 18; ++it) {
            int idx = tid + it * 256;
            int t = idx / 768, r = idx % 768;
            int o = r >> 3, c16 = r & 7;
            cpa16(WB + t * WTILE + o * WROW + c16 * 16,
                  Wsrc[t] + (size_t)o * CIN + c0 + c16 * 8);
        }
        CP_COMMIT();
#pragma unroll
        for (int it = 0; it < 8; ++it) {
            int idx = tid + it * 256;
            int c = idx >> 5, l4 = idx & 31;
            float4 v = *(const float4*)(xb + (size_t)(c0 + c) * LSEQ + l4 * 4);
            split4(Xh, Xl, c * XP + l4 * 4, v);
        }
        CP_WAIT0();
        __syncthreads();

#pragma unroll
        for (int ks = 0; ks < 4; ++ks) {
            uint32_t A[4][4], L[4][4];
            const uint32_t arow = (ks * 16 + kla) * XP;
#pragma unroll
            for (int mf = 0; mf < 4; ++mf) {
                ldsm4t(A[mf], XhS + (arow + mla + mf * 16) * 2);
                ldsm4t(L[mf], XlS + (arow + mla + mf * 16) * 2);
            }
#pragma unroll
            for (int w = 0; w < 3; ++w) {
                const uint32_t whS = WB + (w * 2) * WTILE;
                const uint32_t wlS = whS + WTILE;
                uint32_t Bf[3][2];
#pragma unroll
                for (int nf = 0; nf < 3; ++nf)
                    ldsm2(Bf[nf], whS + bofs + nf * 8 * WROW + ks * 32);
#pragma unroll
                for (int mf = 0; mf < 4; ++mf)
#pragma unroll
                    for (int nf = 0; nf < 3; ++nf) mma_bf16(D[w][mf][nf], A[mf], Bf[nf]);
#pragma unroll
                for (int mf = 0; mf < 4; ++mf)
#pragma unroll
                    for (int nf = 0; nf < 3; ++nf) mma_bf16(D[w][mf][nf], L[mf], Bf[nf]);
#pragma unroll
                for (int nf = 0; nf < 3; ++nf)
                    ldsm2(Bf[nf], wlS + bofs + nf * 8 * WROW + ks * 32);
#pragma unroll
                for (int mf = 0; mf < 4; ++mf)
#pragma unroll
                    for (int nf = 0; nf < 3; ++nf) mma_bf16(D[w][mf][nf], A[mf], Bf[nf]);
            }
        }
    }

    __nv_bfloat16* OH[3] = {g_Qh, g_Kh, g_Vh};
    __nv_bfloat16* OL[3] = {g_Ql, g_Kl, g_Vl};
#pragma unroll
    for (int w = 0; w < 3; ++w) {
#pragma unroll
        for (int mf = 0; mf < 4; ++mf) {
            int row = wm * 64 + mf * 16 + gr;
            size_t rb = ((size_t)b * LSEQ + l0 + row) * CH;
#pragma unroll
            for (int nf = 0; nf < 3; ++nf) {
                int col = wn * 24 + nf * 8 + c2;
                uint32_t h, l;
                split2pack(D[w][mf][nf][0], D[w][mf][nf][1], h, l);
                *(uint32_t*)(OH[w] + rb + col) = h;
                *(uint32_t*)(OL[w] + rb + col) = l;
                split2pack(D[w][mf][nf][2], D[w][mf][nf][3], h, l);
                *(uint32_t*)(OH[w] + rb + 8 * CH + col) = h;
                *(uint32_t*)(OL[w] + rb + 8 * CH + col) = l;
            }
        }
    }
}

// ============================================================================
// Kernel 2: fused flash attention, 512 threads / 16 warps (4 warps per SMSP
// for latency hiding). 256-query tile, 64-key chunks, double-buffered cp.async.
// Q resident in smem (re-ldsm per k-step); ~120 regs/thread under the 128 cap.
// smem: Qh 53248 | Ql 53248 | 2 KV buffers x 4 tiles x 13312 = 212992 B
// ============================================================================
#define FAP 104
#define QREG (256 * FAP * 2)          // 53248 per Q half
#define KTPB (64 * FAP * 2)           // 13312 per K/V tile
#define KVBUF (4 * KTPB)              // 53248 per buffer
#define FA_SMEM (2 * QREG + 2 * KVBUF)  // 212992

__global__ __launch_bounds__(512, 1) void fattn_kernel() {
    extern __shared__ char smraw[];
    const uint32_t base = s2u(smraw);
    const uint32_t QhS = base, QlS = base + QREG, KVB = base + 2 * QREG;
    const int tid = threadIdx.x, wid = tid >> 5, lane = tid & 31;
    const int b = blockIdx.y, q0 = blockIdx.x * 256;
    const int gr = lane >> 2, c2 = (lane & 3) * 2;

    // ---- stage Q hi/lo (resident for whole kernel)
    {
        const __nv_bfloat16* Qh = g_Qh + ((size_t)b * LSEQ + q0) * CH;
        const __nv_bfloat16* Ql = g_Ql + ((size_t)b * LSEQ + q0) * CH;
#pragma unroll
        for (int it = 0; it < 6; ++it) {
            int idx = tid + it * 512;
            int r = idx / 12, c16 = idx % 12;
            cpa16(QhS + r * 208 + c16 * 16, Qh + (size_t)r * CH + c16 * 8);
            cpa16(QlS + r * 208 + c16 * 16, Ql + (size_t)r * CH + c16 * 8);
        }
        CP_COMMIT();
    }

    float O[12][4];
#pragma unroll
    for (int nf = 0; nf < 12; ++nf)
#pragma unroll
        for (int e = 0; e < 4; ++e) O[nf][e] = 0.f;
    float m0 = -1e30f, m1 = -1e30f, l0s = 0.f, l1s = 0.f;

    const __nv_bfloat16* srcs[4] = {
        g_Kh + (size_t)b * LSEQ * CH, g_Kl + (size_t)b * LSEQ * CH,
        g_Vh + (size_t)b * LSEQ * CH, g_Vl + (size_t)b * LSEQ * CH };

    // lane addressing
    const uint32_t arowQ = ((wid * 16 + (lane & 15)) * FAP + ((lane >> 4) << 3)) * 2;
    const uint32_t bofsK4 = (lane & 7) * 208 + ((lane >> 3) & 1) * 16 + (lane >> 4) * 8 * 208;
    const uint32_t browV4 = (lane & 15) * 208 + (lane >> 4) * 16;

    auto issue = [&](int ct, uint32_t bufbase) {
        const int k0 = (ct & 63) * 64;
#pragma unroll
        for (int it = 0; it < 6; ++it) {
            int idx = tid + it * 512;
            int tile = idx / 768, w = idx % 768;
            int r = w / 12, c16 = w % 12;
            cpa16(bufbase + tile * KTPB + r * 208 + c16 * 16,
                  srcs[tile] + (size_t)(k0 + r) * CH + c16 * 8);
        }
        CP_COMMIT();
    };

    issue(0, KVB);
    issue(1, KVB + KVBUF);
    CP_WAIT1();        // Q + chunk0 resident (groups: Q, c0, c1 -> wait leaves <=1)
    __syncthreads();

    for (int ct = 0; ct < 64; ++ct) {
        const uint32_t buf = KVB + (ct & 1) * KVBUF;
        const uint32_t KhS = buf, KlS = buf + KTPB, VhS = buf + 2 * KTPB, VlS = buf + 3 * KTPB;

        // ---- S = Q K^T (split-3), warp tile 16 x 64
        float S[8][4];
#pragma unroll
        for (int nf = 0; nf < 8; ++nf)
#pragma unroll
            for (int e = 0; e < 4; ++e) S[nf][e] = 0.f;

#pragma unroll
        for (int ks = 0; ks < 6; ++ks) {
            uint32_t QH[4], QL[4], Bf[8][2];
            ldsm4(QH, QhS + arowQ + ks * 32);
            ldsm4(QL, QlS + arowQ + ks * 32);
#pragma unroll
            for (int p = 0; p < 4; ++p) {
                uint32_t r4[4];
                ldsm4(r4, KhS + bofsK4 + p * 16 * 208 + ks * 32);
                Bf[2 * p][0] = r4[0]; Bf[2 * p][1] = r4[1];
                Bf[2 * p + 1][0] = r4[2]; Bf[2 * p + 1][1] = r4[3];
            }
#pragma unroll
            for (int nf = 0; nf < 8; ++nf) mma_bf16(S[nf], QH, Bf[nf]);
#pragma unroll
            for (int nf = 0; nf < 8; ++nf) mma_bf16(S[nf], QL, Bf[nf]);
#pragma unroll
            for (int p = 0; p < 4; ++p) {
                uint32_t r4[4];
                ldsm4(r4, KlS + bofsK4 + p * 16 * 208 + ks * 32);
                Bf[2 * p][0] = r4[0]; Bf[2 * p][1] = r4[1];
                Bf[2 * p + 1][0] = r4[2]; Bf[2 * p + 1][1] = r4[3];
            }
#pragma unroll
            for (int nf = 0; nf < 8; ++nf) mma_bf16(S[nf], QH, Bf[nf]);
        }

        // ---- online softmax (rows gr and gr+8 of this warp's 16)
        float r0 = -1e30f, r1 = -1e30f;
#pragma unroll
        for (int nf = 0; nf < 8; ++nf) {
            r0 = fmaxf(r0, fmaxf(S[nf][0], S[nf][1]));
            r1 = fmaxf(r1, fmaxf(S[nf][2], S[nf][3]));
        }
        r0 = fmaxf(r0, __shfl_xor_sync(0xffffffffu, r0, 1));
        r0 = fmaxf(r0, __shfl_xor_sync(0xffffffffu, r0, 2));
        r1 = fmaxf(r1, __shfl_xor_sync(0xffffffffu, r1, 1));
        r1 = fmaxf(r1, __shfl_xor_sync(0xffffffffu, r1, 2));
        const float nm0 = fmaxf(m0, r0), nm1 = fmaxf(m1, r1);
        const float sc0 = fexp(m0 - nm0), sc1 = fexp(m1 - nm1);
        m0 = nm0; m1 = nm1;

        float ps0 = 0.f, ps1 = 0.f;
#pragma unroll
        for (int nf = 0; nf < 8; ++nf) {
            S[nf][0] = fexp(S[nf][0] - m0);
            S[nf][1] = fexp(S[nf][1] - m0);
            S[nf][2] = fexp(S[nf][2] - m1);
            S[nf][3] = fexp(S[nf][3] - m1);
            ps0 += S[nf][0] + S[nf][1];
            ps1 += S[nf][2] + S[nf][3];
        }
        ps0 += __shfl_xor_sync(0xffffffffu, ps0, 1);
        ps0 += __shfl_xor_sync(0xffffffffu, ps0, 2);
        ps1 += __shfl_xor_sync(0xffffffffu, ps1, 1);
        ps1 += __shfl_xor_sync(0xffffffffu, ps1, 2);
        l0s = l0s * sc0 + ps0;
        l1s = l1s * sc1 + ps1;
#pragma unroll
        for (int nf = 0; nf < 12; ++nf) {
            O[nf][0] *= sc0; O[nf][1] *= sc0;
            O[nf][2] *= sc1; O[nf][3] *= sc1;
        }

        // ---- O += P V (split-3): per 16-key step
#pragma unroll
        for (int ks = 0; ks < 4; ++ks) {
            uint32_t PH[4], PL[4];
            split2pack(S[2 * ks][0],     S[2 * ks][1],     PH[0], PL[0]);
            split2pack(S[2 * ks][2],     S[2 * ks][3],     PH[1], PL[1]);
            split2pack(S[2 * ks + 1][0], S[2 * ks + 1][1], PH[2], PL[2]);
            split2pack(S[2 * ks + 1][2], S[2 * ks + 1][3], PH[3], PL[3]);

            uint32_t Vf[12][2];
            const uint32_t vkr = ks * 16 * 208 + browV4;
#pragma unroll
            for (int p = 0; p < 6; ++p) {
                uint32_t r4[4];
                ldsm4t(r4, VhS + vkr + p * 32);
                Vf[2 * p][0] = r4[0]; Vf[2 * p][1] = r4[1];
                Vf[2 * p + 1][0] = r4[2]; Vf[2 * p + 1][1] = r4[3];
            }
#pragma unroll
            for (int nf = 0; nf < 12; ++nf) mma_bf16(O[nf], PH, Vf[nf]);
#pragma unroll
            for (int nf = 0; nf < 12; ++nf) mma_bf16(O[nf], PL, Vf[nf]);
#pragma unroll
            for (int p = 0; p < 6; ++p) {
                uint32_t r4[4];
                ldsm4t(r4, VlS + vkr + p * 32);
                Vf[2 * p][0] = r4[0]; Vf[2 * p][1] = r4[1];
                Vf[2 * p + 1][0] = r4[2]; Vf[2 * p + 1][1] = r4[3];
            }
#pragma unroll
            for (int nf = 0; nf < 12; ++nf) mma_bf16(O[nf], PH, Vf[nf]);
        }

        __syncthreads();                 // all warps done with this buffer
        issue(ct + 2, buf);              // refill consumed buffer
        CP_WAIT1();                      // previous prefetch (next chunk) done
        __syncthreads();
    }

    // ---- epilogue: normalize, split, write g_Oh/g_Ol
    const float i0 = 1.f / l0s, i1 = 1.f / l1s;
    size_t rb = ((size_t)b * LSEQ + q0 + wid * 16 + gr) * CH;
#pragma unroll
    for (int nf = 0; nf < 12; ++nf) {
        int col = nf * 8 + c2;
        uint32_t h, l;
        split2pack(O[nf][0] * i0, O[nf][1] * i0, h, l);
        *(uint32_t*)(g_Oh + rb + col) = h;
        *(uint32_t*)(g_Ol + rb + col) = l;
        split2pack(O[nf][2] * i1, O[nf][3] * i1, h, l);
        *(uint32_t*)(g_Oh + rb + 8 * CH + col) = h;
        *(uint32_t*)(g_Ol + rb + 8 * CH + col) = l;
    }
}

// ============================================================================
// Kernel 3: y[b,o,l] = gamma * (Wlast . O) + x via split-bf16 MMA (unchanged).
// ============================================================================
#define OM_SMEM (2 * 128 * FAP * 2 + 2 * 96 * FAP * 2)

__global__ __launch_bounds__(256, 2) void outmma_kernel(
    const float* __restrict__ x,
    const float* __restrict__ gammap,
    float* __restrict__ out)
{
    extern __shared__ char smraw[];
    const uint32_t base = s2u(smraw);
    const uint32_t OhS = base, OlS = base + 26624, WhS = base + 53248, WlS = base + 73216;
    float* sst = (float*)smraw;

    const int l0 = blockIdx.x * 128;
    const int o0 = blockIdx.y * 96;
    const int b  = blockIdx.z;
    const int tid = threadIdx.x, wid = tid >> 5, lane = tid & 31;
    const int wm = wid & 1, wn = wid >> 1;
    const int gr = lane >> 2, c2 = (lane & 3) * 2;
    const float gamma = gammap[0];

    {
        const __nv_bfloat16* Oh = g_Oh + ((size_t)b * LSEQ + l0) * CH;
        const __nv_bfloat16* Ol = g_Ol + ((size_t)b * LSEQ + l0) * CH;
#pragma unroll
        for (int it = 0; it < 6; ++it) {
            int idx = tid + it * 256;
            int r = idx / 12, c16 = idx % 12;
            cpa16(OhS + r * 208 + c16 * 16, Oh + (size_t)r * CH + c16 * 8);
            cpa16(OlS + r * 208 + c16 * 16, Ol + (size_t)r * CH + c16 * 8);
        }
        const __nv_bfloat16* Wh = g_Wh + (size_t)o0 * CH;
        const __nv_bfloat16* Wl = g_Wl + (size_t)o0 * CH;
#pragma unroll
        for (int it = 0; it < 5; ++it) {
            int idx = tid + it * 256;
            if (idx < 1152) {
                int r = idx / 12, c16 = idx % 12;
                cpa16(WhS + r * 208 + c16 * 16, Wh + (size_t)r * CH + c16 * 8);
                cpa16(WlS + r * 208 + c16 * 16, Wl + (size_t)r * CH + c16 * 8);
            }
        }
        CP_COMMIT();
        CP_WAIT0();
    }
    __syncthreads();

    const uint32_t aoff = ((wm * 64 + (lane & 15)) * FAP + ((lane >> 4) << 3)) * 2;
    const uint32_t bofs = ((wn * 24 + (lane & 7)) * FAP + (((lane >> 3) & 1) << 3)) * 2;

    float D[4][3][4];
#pragma unroll
    for (int mf = 0; mf < 4; ++mf)
#pragma unroll
        for (int nf = 0; nf < 3; ++nf)
#pragma unroll
            for (int e = 0; e < 4; ++e) D[mf][nf][e] = 0.f;

#pragma unroll
    for (int ks = 0; ks < 6; ++ks) {
        uint32_t A[4][4], L[4][4], Bf[3][2];
#pragma unroll
        for (int mf = 0; mf < 4; ++mf)
            ldsm4(A[mf], OhS + aoff + mf * 16 * (FAP * 2) + ks * 32);
#pragma unroll
        for (int nf = 0; nf < 3; ++nf)
            ldsm2(Bf[nf], WhS + bofs + nf * 8 * (FAP * 2) + ks * 32);
#pragma unroll
        for (int mf = 0; mf < 4; ++mf)
#pragma unroll
            for (int nf = 0; nf < 3; ++nf) mma_bf16(D[mf][nf], A[mf], Bf[nf]);
#pragma unroll
        for (int mf = 0; mf < 4; ++mf)
            ldsm4(L[mf], OlS + aoff + mf * 16 * (FAP * 2) + ks * 32);
#pragma unroll
        for (int mf = 0; mf < 4; ++mf)
#pragma unroll
            for (int nf = 0; nf < 3; ++nf) mma_bf16(D[mf][nf], L[mf], Bf[nf]);
#pragma unroll
        for (int nf = 0; nf < 3; ++nf)
            ldsm2(Bf[nf], WlS + bofs + nf * 8 * (FAP * 2) + ks * 32);
#pragma unroll
        for (int mf = 0; mf < 4; ++mf)
#pragma unroll
            for (int nf = 0; nf < 3; ++nf) mma_bf16(D[mf][nf], A[mf], Bf[nf]);
    }
    __syncthreads();

#pragma unroll
    for (int mf = 0; mf < 4; ++mf) {
        int row = wm * 64 + mf * 16 + gr;
#pragma unroll
        for (int nf = 0; nf < 3; ++nf) {
            int col = wn * 24 + nf * 8 + c2;
            sst[(col)     * 132 + row]     = D[mf][nf][0];
            sst[(col + 1) * 132 + row]     = D[mf][nf][1];
            sst[(col)     * 132 + row + 8] = D[mf][nf][2];
            sst[(col + 1) * 132 + row + 8] = D[mf][nf][3];
        }
    }
    __syncthreads();

#pragma unroll
    for (int it = 0; it < 12; ++it) {
        int idx = tid + it * 256;
        int o = idx >> 5, l4 = idx & 31;
        float4 v = *(const float4*)&sst[o * 132 + l4 * 4];
        size_t gbase = (size_t)b * COUTC * LSEQ + (size_t)(o0 + o) * LSEQ + l0 + l4 * 4;
        float4 xr = *(const float4*)(x + gbase);
        *(float4*)(out + gbase) = make_float4(fmaf(gamma, v.x, xr.x),
                                              fmaf(gamma, v.y, xr.y),
                                              fmaf(gamma, v.z, xr.z),
                                              fmaf(gamma, v.w, xr.w));
    }
}

// ============================================================================
extern "C" void kernel_launch(void* const* d_in, const int* in_sizes, int n_in,
                              void* d_out, int out_size) {
    const float* x     = (const float*)d_in[0];
    const float* Wq    = (const float*)d_in[1];
    const float* Wk    = (const float*)d_in[2];
    const float* Wv    = (const float*)d_in[3];
    const float* Wl    = (const float*)d_in[4];
    const float* gamma = (const float*)d_in[5];
    float* out = (float*)d_out;

    cudaFuncSetAttribute(projmma_kernel, cudaFuncAttributeMaxDynamicSharedMemorySize, PJ_SMEM);
    cudaFuncSetAttribute(fattn_kernel,   cudaFuncAttributeMaxDynamicSharedMemorySize, FA_SMEM);
    cudaFuncSetAttribute(outmma_kernel,  cudaFuncAttributeMaxDynamicSharedMemorySize, OM_SMEM);

    wsplit_kernel<<<288, 256>>>(Wq, Wk, Wv, Wl);
    projmma_kernel<<<dim3(32, 1, 8), 256, PJ_SMEM>>>(x);
    fattn_kernel<<<dim3(16, 8), 512, FA_SMEM>>>();
    outmma_kernel<<<dim3(32, 8, 8), 256, OM_SMEM>>>(x, gamma, out);
}

// round 12
// speedup vs baseline: 3.5076x; 1.0400x over previous
#include <cuda_runtime.h>
#include <cuda_bf16.h>
#include <cstdint>
#include <cstddef>

#define BB    8
#define CIN   768
#define LSEQ  4096
#define CH    96
#define COUTC 768

// ---- device-global scratch: pre-split bf16 hi/lo pairs ----
__device__ __nv_bfloat16 g_Qh[BB * LSEQ * CH], g_Ql[BB * LSEQ * CH];
__device__ __nv_bfloat16 g_Kh[BB * LSEQ * CH], g_Kl[BB * LSEQ * CH];
__device__ __nv_bfloat16 g_Vh[BB * LSEQ * CH], g_Vl[BB * LSEQ * CH];
__device__ __nv_bfloat16 g_Oh[BB * LSEQ * CH], g_Ol[BB * LSEQ * CH];
__device__ __nv_bfloat16 g_Wh[COUTC * CH],     g_Wl[COUTC * CH];
__device__ __nv_bfloat16 g_Wqh[CH * CIN], g_Wql[CH * CIN];
__device__ __nv_bfloat16 g_Wkh[CH * CIN], g_Wkl[CH * CIN];
__device__ __nv_bfloat16 g_Wvh[CH * CIN], g_Wvl[CH * CIN];

// ============================================================================
// PTX helpers
// ============================================================================
__device__ __forceinline__ uint32_t s2u(const void* p) {
    return (uint32_t)__cvta_generic_to_shared(p);
}
__device__ __forceinline__ void ldsm4(uint32_t r[4], uint32_t a) {
    asm volatile("ldmatrix.sync.aligned.m8n8.x4.shared.b16 {%0,%1,%2,%3}, [%4];"
                 : "=r"(r[0]), "=r"(r[1]), "=r"(r[2]), "=r"(r[3]) : "r"(a));
}
__device__ __forceinline__ void ldsm4t(uint32_t r[4], uint32_t a) {
    asm volatile("ldmatrix.sync.aligned.m8n8.x4.trans.shared.b16 {%0,%1,%2,%3}, [%4];"
                 : "=r"(r[0]), "=r"(r[1]), "=r"(r[2]), "=r"(r[3]) : "r"(a));
}
__device__ __forceinline__ void ldsm2(uint32_t r[2], uint32_t a) {
    asm volatile("ldmatrix.sync.aligned.m8n8.x2.shared.b16 {%0,%1}, [%2];"
                 : "=r"(r[0]), "=r"(r[1]) : "r"(a));
}
__device__ __forceinline__ void mma_bf16(float d[4], const uint32_t a[4], const uint32_t b[2]) {
    asm volatile("mma.sync.aligned.m16n8k16.row.col.f32.bf16.bf16.f32 "
                 "{%0,%1,%2,%3}, {%4,%5,%6,%7}, {%8,%9}, {%0,%1,%2,%3};"
                 : "+f"(d[0]), "+f"(d[1]), "+f"(d[2]), "+f"(d[3])
                 : "r"(a[0]), "r"(a[1]), "r"(a[2]), "r"(a[3]), "r"(b[0]), "r"(b[1]));
}
__device__ __forceinline__ void cpa16(uint32_t dst, const void* src) {
    asm volatile("cp.async.cg.shared.global [%0], [%1], 16;" :: "r"(dst), "l"(src));
}
#define CP_COMMIT() asm volatile("cp.async.commit_group;" ::: "memory")
#define CP_WAIT0()  asm volatile("cp.async.wait_group 0;" ::: "memory")
#define CP_WAIT1()  asm volatile("cp.async.wait_group 1;" ::: "memory")

__device__ __forceinline__ void split4(__nv_bfloat16* hiB, __nv_bfloat16* loB,
                                       int eoff, float4 v) {
    float f[4] = {v.x, v.y, v.z, v.w};
    unsigned short h[4], l[4];
#pragma unroll
    for (int i = 0; i < 4; ++i) {
        __nv_bfloat16 hb = __float2bfloat16(f[i]);
        float r = f[i] - __bfloat162float(hb);
        h[i] = __bfloat16_as_ushort(hb);
        l[i] = __bfloat16_as_ushort(__float2bfloat16(r));
    }
    *(uint2*)(hiB + eoff) = make_uint2((uint32_t)h[0] | ((uint32_t)h[1] << 16),
                                       (uint32_t)h[2] | ((uint32_t)h[3] << 16));
    *(uint2*)(loB + eoff) = make_uint2((uint32_t)l[0] | ((uint32_t)l[1] << 16),
                                       (uint32_t)l[2] | ((uint32_t)l[3] << 16));
}
__device__ __forceinline__ void split2pack(float a, float b, uint32_t& hi, uint32_t& lo) {
    __nv_bfloat16 ah = __float2bfloat16(a), bh = __float2bfloat16(b);
    float ar = a - __bfloat162float(ah);
    float br = b - __bfloat162float(bh);
    hi = (uint32_t)__bfloat16_as_ushort(ah) | ((uint32_t)__bfloat16_as_ushort(bh) << 16);
    lo = (uint32_t)__bfloat16_as_ushort(__float2bfloat16(ar)) |
         ((uint32_t)__bfloat16_as_ushort(__float2bfloat16(br)) << 16);
}
__device__ __forceinline__ float fexp(float x) {
    float y = x * 1.4426950408889634f;
    y = fmaxf(y, -126.0f);
    float t = y + 12582912.0f;
    float f = y - (t - 12582912.0f);
    float p =            1.3333558146e-3f;
    p = fmaf(p, f, 9.6181291076e-3f);
    p = fmaf(p, f, 5.5504108664e-2f);
    p = fmaf(p, f, 2.4022650696e-1f);
    p = fmaf(p, f, 6.9314718056e-1f);
    p = fmaf(p, f, 1.0f);
    int e = (__float_as_int(t) - 0x4b400000 + 127) << 23;
    return p * __int_as_float(e);
}

// ============================================================================
// Kernel 0: split all 4 weight matrices into bf16 hi/lo.
// ============================================================================
__global__ __launch_bounds__(256) void wsplit_kernel(
    const float* __restrict__ Wq, const float* __restrict__ Wk,
    const float* __restrict__ Wv, const float* __restrict__ Wlast)
{
    int g = blockIdx.x * 256 + threadIdx.x;
    int m = g / 18432, idx = g % 18432;
    const float* src = (m == 0) ? Wq : (m == 1) ? Wk : (m == 2) ? Wv : Wlast;
    __nv_bfloat16 *dh, *dl;
    if (m == 0)      { dh = g_Wqh; dl = g_Wql; }
    else if (m == 1) { dh = g_Wkh; dl = g_Wkl; }
    else if (m == 2) { dh = g_Wvh; dl = g_Wvl; }
    else             { dh = g_Wh;  dl = g_Wl;  }
    float4 v = *(const float4*)(src + idx * 4);
    split4(dh, dl, idx * 4, v);
}

// ============================================================================
// Kernel 1: fused QKV projection (unchanged).
// ============================================================================
#define XP 136
#define WROW 144
#define WTILE (96 * WROW)
#define PJ_WBASE (2 * 64 * XP * 2)
#define PJ_SMEM (PJ_WBASE + 6 * WTILE)

__global__ __launch_bounds__(256, 1) void projmma_kernel(const float* __restrict__ x) {
    extern __shared__ char smraw[];
    __nv_bfloat16* Xh = (__nv_bfloat16*)smraw;
    __nv_bfloat16* Xl = Xh + 64 * XP;
    const uint32_t base = s2u(smraw);
    const uint32_t XhS = base, XlS = base + 17408, WB = base + PJ_WBASE;

    const int l0 = blockIdx.x * 128;
    const int b  = blockIdx.z;
    const int tid = threadIdx.x, wid = tid >> 5, lane = tid & 31;
    const int wm = wid & 1, wn = wid >> 1;

    const int gr = lane >> 2, c2 = (lane & 3) * 2;
    const uint32_t kla = (lane & 7) + ((lane >> 4) << 3);
    const uint32_t mla = ((lane >> 3) & 1) * 8 + wm * 64;
    const uint32_t bofs = ((wn * 24 + (lane & 7)) * 72 + (((lane >> 3) & 1) << 3)) * 2;

    const __nv_bfloat16* Wsrc[6] = {g_Wqh, g_Wql, g_Wkh, g_Wkl, g_Wvh, g_Wvl};

    float D[3][4][3][4];
#pragma unroll
    for (int w = 0; w < 3; ++w)
#pragma unroll
        for (int mf = 0; mf < 4; ++mf)
#pragma unroll
            for (int nf = 0; nf < 3; ++nf)
#pragma unroll
                for (int e = 0; e < 4; ++e) D[w][mf][nf][e] = 0.f;

    const float* xb = x + (size_t)b * CIN * LSEQ + l0;

    for (int c0 = 0; c0 < CIN; c0 += 64) {
        __syncthreads();
#pragma unroll
        for (int it = 0; it < 18; ++it) {
            int idx = tid + it * 256;
            int t = idx / 768, r = idx % 768;
            int o = r >> 3, c16 = r & 7;
            cpa16(WB + t * WTILE + o * WROW + c16 * 16,
                  Wsrc[t] + (size_t)o * CIN + c0 + c16 * 8);
        }
        CP_COMMIT();
#pragma unroll
        for (int it = 0; it < 8; ++it) {
            int idx = tid + it * 256;
            int c = idx >> 5, l4 = idx & 31;
            float4 v = *(const float4*)(xb + (size_t)(c0 + c) * LSEQ + l4 * 4);
            split4(Xh, Xl, c * XP + l4 * 4, v);
        }
        CP_WAIT0();
        __syncthreads();

#pragma unroll
        for (int ks = 0; ks < 4; ++ks) {
            uint32_t A[4][4], L[4][4];
            const uint32_t arow = (ks * 16 + kla) * XP;
#pragma unroll
            for (int mf = 0; mf < 4; ++mf) {
                ldsm4t(A[mf], XhS + (arow + mla + mf * 16) * 2);
                ldsm4t(L[mf], XlS + (arow + mla + mf * 16) * 2);
            }
#pragma unroll
            for (int w = 0; w < 3; ++w) {
                const uint32_t whS = WB + (w * 2) * WTILE;
                const uint32_t wlS = whS + WTILE;
                uint32_t Bf[3][2];
#pragma unroll
                for (int nf = 0; nf < 3; ++nf)
                    ldsm2(Bf[nf], whS + bofs + nf * 8 * WROW + ks * 32);
#pragma unroll
                for (int mf = 0; mf < 4; ++mf)
#pragma unroll
                    for (int nf = 0; nf < 3; ++nf) mma_bf16(D[w][mf][nf], A[mf], Bf[nf]);
#pragma unroll
                for (int mf = 0; mf < 4; ++mf)
#pragma unroll
                    for (int nf = 0; nf < 3; ++nf) mma_bf16(D[w][mf][nf], L[mf], Bf[nf]);
#pragma unroll
                for (int nf = 0; nf < 3; ++nf)
                    ldsm2(Bf[nf], wlS + bofs + nf * 8 * WROW + ks * 32);
#pragma unroll
                for (int mf = 0; mf < 4; ++mf)
#pragma unroll
                    for (int nf = 0; nf < 3; ++nf) mma_bf16(D[w][mf][nf], A[mf], Bf[nf]);
            }
        }
    }

    __nv_bfloat16* OH[3] = {g_Qh, g_Kh, g_Vh};
    __nv_bfloat16* OL[3] = {g_Ql, g_Kl, g_Vl};
#pragma unroll
    for (int w = 0; w < 3; ++w) {
#pragma unroll
        for (int mf = 0; mf < 4; ++mf) {
            int row = wm * 64 + mf * 16 + gr;
            size_t rb = ((size_t)b * LSEQ + l0 + row) * CH;
#pragma unroll
            for (int nf = 0; nf < 3; ++nf) {
                int col = wn * 24 + nf * 8 + c2;
                uint32_t h, l;
                split2pack(D[w][mf][nf][0], D[w][mf][nf][1], h, l);
                *(uint32_t*)(OH[w] + rb + col) = h;
                *(uint32_t*)(OL[w] + rb + col) = l;
                split2pack(D[w][mf][nf][2], D[w][mf][nf][3], h, l);
                *(uint32_t*)(OH[w] + rb + 8 * CH + col) = h;
                *(uint32_t*)(OL[w] + rb + 8 * CH + col) = l;
            }
        }
    }
}

// ============================================================================
// Kernel 2: fused flash attention, M=32 warp tiles: 256 threads / 8 warps,
// 256-query tile. K/V fragments amortized over 2 M-frags per warp, cutting
// redundant LDS traffic ~45%. 64-key chunks, double-buffered cp.async.
// smem: Qh 53248 | Ql 53248 | 2 KV buffers x 4 tiles x 13312 = 212992 B
// ============================================================================
#define FAP 104
#define QREG (256 * FAP * 2)
#define KTPB (64 * FAP * 2)
#define KVBUF (4 * KTPB)
#define FA_SMEM (2 * QREG + 2 * KVBUF)

__global__ __launch_bounds__(256, 1) void fattn_kernel() {
    extern __shared__ char smraw[];
    const uint32_t base = s2u(smraw);
    const uint32_t QhS = base, QlS = base + QREG, KVB = base + 2 * QREG;
    const int tid = threadIdx.x, wid = tid >> 5, lane = tid & 31;
    const int b = blockIdx.y, q0 = blockIdx.x * 256;
    const int gr = lane >> 2, c2 = (lane & 3) * 2;

    // ---- stage Q hi/lo (resident for whole kernel)
    {
        const __nv_bfloat16* Qh = g_Qh + ((size_t)b * LSEQ + q0) * CH;
        const __nv_bfloat16* Ql = g_Ql + ((size_t)b * LSEQ + q0) * CH;
#pragma unroll
        for (int it = 0; it < 12; ++it) {
            int idx = tid + it * 256;
            int r = idx / 12, c16 = idx % 12;
            cpa16(QhS + r * 208 + c16 * 16, Qh + (size_t)r * CH + c16 * 8);
            cpa16(QlS + r * 208 + c16 * 16, Ql + (size_t)r * CH + c16 * 8);
        }
        CP_COMMIT();
    }

    float O[2][12][4];
#pragma unroll
    for (int mf = 0; mf < 2; ++mf)
#pragma unroll
        for (int nf = 0; nf < 12; ++nf)
#pragma unroll
            for (int e = 0; e < 4; ++e) O[mf][nf][e] = 0.f;
    float m[4], ls[4];
#pragma unroll
    for (int i = 0; i < 4; ++i) { m[i] = -1e30f; ls[i] = 0.f; }

    const __nv_bfloat16* srcs[4] = {
        g_Kh + (size_t)b * LSEQ * CH, g_Kl + (size_t)b * LSEQ * CH,
        g_Vh + (size_t)b * LSEQ * CH, g_Vl + (size_t)b * LSEQ * CH };

    // lane addressing: warp owns rows [wid*32, wid*32+32)
    const uint32_t arowQ = ((wid * 32 + (lane & 15)) * FAP + ((lane >> 4) << 3)) * 2;
    const uint32_t bofsK4 = (lane & 7) * 208 + ((lane >> 3) & 1) * 16 + (lane >> 4) * 8 * 208;
    const uint32_t browV4 = (lane & 15) * 208 + (lane >> 4) * 16;

    auto issue = [&](int ct, uint32_t bufbase) {
        const int k0 = (ct & 63) * 64;
#pragma unroll
        for (int it = 0; it < 12; ++it) {
            int idx = tid + it * 256;
            int tile = idx / 768, w = idx % 768;
            int r = w / 12, c16 = w % 12;
            cpa16(bufbase + tile * KTPB + r * 208 + c16 * 16,
                  srcs[tile] + (size_t)(k0 + r) * CH + c16 * 8);
        }
        CP_COMMIT();
    };

    issue(0, KVB);
    issue(1, KVB + KVBUF);
    CP_WAIT1();
    __syncthreads();

    for (int ct = 0; ct < 64; ++ct) {
        const uint32_t buf = KVB + (ct & 1) * KVBUF;
        const uint32_t KhS = buf, KlS = buf + KTPB, VhS = buf + 2 * KTPB, VlS = buf + 3 * KTPB;

        // ---- S = Q K^T (split-3), warp tile 32 x 64
        float S[2][8][4];
#pragma unroll
        for (int mf = 0; mf < 2; ++mf)
#pragma unroll
            for (int nf = 0; nf < 8; ++nf)
#pragma unroll
                for (int e = 0; e < 4; ++e) S[mf][nf][e] = 0.f;

#pragma unroll
        for (int ks = 0; ks < 6; ++ks) {
            uint32_t QH0[4], QH1[4], QL0[4], QL1[4], Bf[8][2];
            ldsm4(QH0, QhS + arowQ + ks * 32);
            ldsm4(QH1, QhS + arowQ + 16 * 208 + ks * 32);
            ldsm4(QL0, QlS + arowQ + ks * 32);
            ldsm4(QL1, QlS + arowQ + 16 * 208 + ks * 32);
#pragma unroll
            for (int p = 0; p < 4; ++p) {
                uint32_t r4[4];
                ldsm4(r4, KhS + bofsK4 + p * 16 * 208 + ks * 32);
                Bf[2 * p][0] = r4[0]; Bf[2 * p][1] = r4[1];
                Bf[2 * p + 1][0] = r4[2]; Bf[2 * p + 1][1] = r4[3];
            }
#pragma unroll
            for (int nf = 0; nf < 8; ++nf) {
                mma_bf16(S[0][nf], QH0, Bf[nf]);
                mma_bf16(S[1][nf], QH1, Bf[nf]);
            }
#pragma unroll
            for (int nf = 0; nf < 8; ++nf) {
                mma_bf16(S[0][nf], QL0, Bf[nf]);
                mma_bf16(S[1][nf], QL1, Bf[nf]);
            }
#pragma unroll
            for (int p = 0; p < 4; ++p) {
                uint32_t r4[4];
                ldsm4(r4, KlS + bofsK4 + p * 16 * 208 + ks * 32);
                Bf[2 * p][0] = r4[0]; Bf[2 * p][1] = r4[1];
                Bf[2 * p + 1][0] = r4[2]; Bf[2 * p + 1][1] = r4[3];
            }
#pragma unroll
            for (int nf = 0; nf < 8; ++nf) {
                mma_bf16(S[0][nf], QH0, Bf[nf]);
                mma_bf16(S[1][nf], QH1, Bf[nf]);
            }
        }

        // ---- online softmax per M-frag (rows mf*16+gr and mf*16+8+gr)
#pragma unroll
        for (int mf = 0; mf < 2; ++mf) {
            float r0 = -1e30f, r1 = -1e30f;
#pragma unroll
            for (int nf = 0; nf < 8; ++nf) {
                r0 = fmaxf(r0, fmaxf(S[mf][nf][0], S[mf][nf][1]));
                r1 = fmaxf(r1, fmaxf(S[mf][nf][2], S[mf][nf][3]));
            }
            r0 = fmaxf(r0, __shfl_xor_sync(0xffffffffu, r0, 1));
            r0 = fmaxf(r0, __shfl_xor_sync(0xffffffffu, r0, 2));
            r1 = fmaxf(r1, __shfl_xor_sync(0xffffffffu, r1, 1));
            r1 = fmaxf(r1, __shfl_xor_sync(0xffffffffu, r1, 2));
            const float nm0 = fmaxf(m[2 * mf], r0), nm1 = fmaxf(m[2 * mf + 1], r1);
            const float sc0 = fexp(m[2 * mf] - nm0), sc1 = fexp(m[2 * mf + 1] - nm1);
            m[2 * mf] = nm0; m[2 * mf + 1] = nm1;

            float ps0 = 0.f, ps1 = 0.f;
#pragma unroll
            for (int nf = 0; nf < 8; ++nf) {
                S[mf][nf][0] = fexp(S[mf][nf][0] - nm0);
                S[mf][nf][1] = fexp(S[mf][nf][1] - nm0);
                S[mf][nf][2] = fexp(S[mf][nf][2] - nm1);
                S[mf][nf][3] = fexp(S[mf][nf][3] - nm1);
                ps0 += S[mf][nf][0] + S[mf][nf][1];
                ps1 += S[mf][nf][2] + S[mf][nf][3];
            }
            ps0 += __shfl_xor_sync(0xffffffffu, ps0, 1);
            ps0 += __shfl_xor_sync(0xffffffffu, ps0, 2);
            ps1 += __shfl_xor_sync(0xffffffffu, ps1, 1);
            ps1 += __shfl_xor_sync(0xffffffffu, ps1, 2);
            ls[2 * mf]     = ls[2 * mf] * sc0 + ps0;
            ls[2 * mf + 1] = ls[2 * mf + 1] * sc1 + ps1;
#pragma unroll
            for (int nf = 0; nf < 12; ++nf) {
                O[mf][nf][0] *= sc0; O[mf][nf][1] *= sc0;
                O[mf][nf][2] *= sc1; O[mf][nf][3] *= sc1;
            }
        }

        // ---- O += P V (split-3): V fragments shared by both M-frags
#pragma unroll
        for (int ks = 0; ks < 4; ++ks) {
            uint32_t PH0[4], PL0[4], PH1[4], PL1[4];
            split2pack(S[0][2 * ks][0],     S[0][2 * ks][1],     PH0[0], PL0[0]);
            split2pack(S[0][2 * ks][2],     S[0][2 * ks][3],     PH0[1], PL0[1]);
            split2pack(S[0][2 * ks + 1][0], S[0][2 * ks + 1][1], PH0[2], PL0[2]);
            split2pack(S[0][2 * ks + 1][2], S[0][2 * ks + 1][3], PH0[3], PL0[3]);
            split2pack(S[1][2 * ks][0],     S[1][2 * ks][1],     PH1[0], PL1[0]);
            split2pack(S[1][2 * ks][2],     S[1][2 * ks][3],     PH1[1], PL1[1]);
            split2pack(S[1][2 * ks + 1][0], S[1][2 * ks + 1][1], PH1[2], PL1[2]);
            split2pack(S[1][2 * ks + 1][2], S[1][2 * ks + 1][3], PH1[3], PL1[3]);

            uint32_t Vf[12][2];
            const uint32_t vkr = ks * 16 * 208 + browV4;
#pragma unroll
            for (int p = 0; p < 6; ++p) {
                uint32_t r4[4];
                ldsm4t(r4, VhS + vkr + p * 32);
                Vf[2 * p][0] = r4[0]; Vf[2 * p][1] = r4[1];
                Vf[2 * p + 1][0] = r4[2]; Vf[2 * p + 1][1] = r4[3];
            }
#pragma unroll
            for (int nf = 0; nf < 12; ++nf) {
                mma_bf16(O[0][nf], PH0, Vf[nf]);
                mma_bf16(O[1][nf], PH1, Vf[nf]);
            }
#pragma unroll
            for (int nf = 0; nf < 12; ++nf) {
                mma_bf16(O[0][nf], PL0, Vf[nf]);
                mma_bf16(O[1][nf], PL1, Vf[nf]);
            }
#pragma unroll
            for (int p = 0; p < 6; ++p) {
                uint32_t r4[4];
                ldsm4t(r4, VlS + vkr + p * 32);
                Vf[2 * p][0] = r4[0]; Vf[2 * p][1] = r4[1];
                Vf[2 * p + 1][0] = r4[2]; Vf[2 * p + 1][1] = r4[3];
            }
#pragma unroll
            for (int nf = 0; nf < 12; ++nf) {
                mma_bf16(O[0][nf], PH0, Vf[nf]);
                mma_bf16(O[1][nf], PH1, Vf[nf]);
            }
        }

        __syncthreads();
        issue(ct + 2, buf);
        CP_WAIT1();
        __syncthreads();
    }

    // ---- epilogue: normalize, split, write g_Oh/g_Ol
#pragma unroll
    for (int mf = 0; mf < 2; ++mf) {
        const float i0 = 1.f / ls[2 * mf], i1 = 1.f / ls[2 * mf + 1];
        size_t rb = ((size_t)b * LSEQ + q0 + wid * 32 + mf * 16 + gr) * CH;
#pragma unroll
        for (int nf = 0; nf < 12; ++nf) {
            int col = nf * 8 + c2;
            uint32_t h, l;
            split2pack(O[mf][nf][0] * i0, O[mf][nf][1] * i0, h, l);
            *(uint32_t*)(g_Oh + rb + col) = h;
            *(uint32_t*)(g_Ol + rb + col) = l;
            split2pack(O[mf][nf][2] * i1, O[mf][nf][3] * i1, h, l);
            *(uint32_t*)(g_Oh + rb + 8 * CH + col) = h;
            *(uint32_t*)(g_Ol + rb + 8 * CH + col) = l;
        }
    }
}

// ============================================================================
// Kernel 3: y[b,o,l] = gamma * (Wlast . O) + x via split-bf16 MMA (unchanged).
// ============================================================================
#define OM_SMEM (2 * 128 * FAP * 2 + 2 * 96 * FAP * 2)

__global__ __launch_bounds__(256, 2) void outmma_kernel(
    const float* __restrict__ x,
    const float* __restrict__ gammap,
    float* __restrict__ out)
{
    extern __shared__ char smraw[];
    const uint32_t base = s2u(smraw);
    const uint32_t OhS = base, OlS = base + 26624, WhS = base + 53248, WlS = base + 73216;
    float* sst = (float*)smraw;

    const int l0 = blockIdx.x * 128;
    const int o0 = blockIdx.y * 96;
    const int b  = blockIdx.z;
    const int tid = threadIdx.x, wid = tid >> 5, lane = tid & 31;
    const int wm = wid & 1, wn = wid >> 1;
    const int gr = lane >> 2, c2 = (lane & 3) * 2;
    const float gamma = gammap[0];

    {
        const __nv_bfloat16* Oh = g_Oh + ((size_t)b * LSEQ + l0) * CH;
        const __nv_bfloat16* Ol = g_Ol + ((size_t)b * LSEQ + l0) * CH;
#pragma unroll
        for (int it = 0; it < 6; ++it) {
            int idx = tid + it * 256;
            int r = idx / 12, c16 = idx % 12;
            cpa16(OhS + r * 208 + c16 * 16, Oh + (size_t)r * CH + c16 * 8);
            cpa16(OlS + r * 208 + c16 * 16, Ol + (size_t)r * CH + c16 * 8);
        }
        const __nv_bfloat16* Wh = g_Wh + (size_t)o0 * CH;
        const __nv_bfloat16* Wl = g_Wl + (size_t)o0 * CH;
#pragma unroll
        for (int it = 0; it < 5; ++it) {
            int idx = tid + it * 256;
            if (idx < 1152) {
                int r = idx / 12, c16 = idx % 12;
                cpa16(WhS + r * 208 + c16 * 16, Wh + (size_t)r * CH + c16 * 8);
                cpa16(WlS + r * 208 + c16 * 16, Wl + (size_t)r * CH + c16 * 8);
            }
        }
        CP_COMMIT();
        CP_WAIT0();
    }
    __syncthreads();

    const uint32_t aoff = ((wm * 64 + (lane & 15)) * FAP + ((lane >> 4) << 3)) * 2;
    const uint32_t bofs = ((wn * 24 + (lane & 7)) * FAP + (((lane >> 3) & 1) << 3)) * 2;

    float D[4][3][4];
#pragma unroll
    for (int mf = 0; mf < 4; ++mf)
#pragma unroll
        for (int nf = 0; nf < 3; ++nf)
#pragma unroll
            for (int e = 0; e < 4; ++e) D[mf][nf][e] = 0.f;

#pragma unroll
    for (int ks = 0; ks < 6; ++ks) {
        uint32_t A[4][4], L[4][4], Bf[3][2];
#pragma unroll
        for (int mf = 0; mf < 4; ++mf)
            ldsm4(A[mf], OhS + aoff + mf * 16 * (FAP * 2) + ks * 32);
#pragma unroll
        for (int nf = 0; nf < 3; ++nf)
            ldsm2(Bf[nf], WhS + bofs + nf * 8 * (FAP * 2) + ks * 32);
#pragma unroll
        for (int mf = 0; mf < 4; ++mf)
#pragma unroll
            for (int nf = 0; nf < 3; ++nf) mma_bf16(D[mf][nf], A[mf], Bf[nf]);
#pragma unroll
        for (int mf = 0; mf < 4; ++mf)
            ldsm4(L[mf], OlS + aoff + mf * 16 * (FAP * 2) + ks * 32);
#pragma unroll
        for (int mf = 0; mf < 4; ++mf)
#pragma unroll
            for (int nf = 0; nf < 3; ++nf) mma_bf16(D[mf][nf], L[mf], Bf[nf]);
#pragma unroll
        for (int nf = 0; nf < 3; ++nf)
            ldsm2(Bf[nf], WlS + bofs + nf * 8 * (FAP * 2) + ks * 32);
#pragma unroll
        for (int mf = 0; mf < 4; ++mf)
#pragma unroll
            for (int nf = 0; nf < 3; ++nf) mma_bf16(D[mf][nf], A[mf], Bf[nf]);
    }
    __syncthreads();

#pragma unroll
    for (int mf = 0; mf < 4; ++mf) {
        int row = wm * 64 + mf * 16 + gr;
#pragma unroll
        for (int nf = 0; nf < 3; ++nf) {
            int col = wn * 24 + nf * 8 + c2;
            sst[(col)     * 132 + row]     = D[mf][nf][0];
            sst[(col + 1) * 132 + row]     = D[mf][nf][1];
            sst[(col)     * 132 + row + 8] = D[mf][nf][2];
            sst[(col + 1) * 132 + row + 8] = D[mf][nf][3];
        }
    }
    __syncthreads();

#pragma unroll
    for (int it = 0; it < 12; ++it) {
        int idx = tid + it * 256;
        int o = idx >> 5, l4 = idx & 31;
        float4 v = *(const float4*)&sst[o * 132 + l4 * 4];
        size_t gbase = (size_t)b * COUTC * LSEQ + (size_t)(o0 + o) * LSEQ + l0 + l4 * 4;
        float4 xr = *(const float4*)(x + gbase);
        *(float4*)(out + gbase) = make_float4(fmaf(gamma, v.x, xr.x),
                                              fmaf(gamma, v.y, xr.y),
                                              fmaf(gamma, v.z, xr.z),
                                              fmaf(gamma, v.w, xr.w));
    }
}

// ============================================================================
extern "C" void kernel_launch(void* const* d_in, const int* in_sizes, int n_in,
                              void* d_out, int out_size) {
    const float* x     = (const float*)d_in[0];
    const float* Wq    = (const float*)d_in[1];
    const float* Wk    = (const float*)d_in[2];
    const float* Wv    = (const float*)d_in[3];
    const float* Wl    = (const float*)d_in[4];
    const float* gamma = (const float*)d_in[5];
    float* out = (float*)d_out;

    cudaFuncSetAttribute(projmma_kernel, cudaFuncAttributeMaxDynamicSharedMemorySize, PJ_SMEM);
    cudaFuncSetAttribute(fattn_kernel,   cudaFuncAttributeMaxDynamicSharedMemorySize, FA_SMEM);
    cudaFuncSetAttribute(outmma_kernel,  cudaFuncAttributeMaxDynamicSharedMemorySize, OM_SMEM);

    wsplit_kernel<<<288, 256>>>(Wq, Wk, Wv, Wl);
    projmma_kernel<<<dim3(32, 1, 8), 256, PJ_SMEM>>>(x);
    fattn_kernel<<<dim3(16, 8), 256, FA_SMEM>>>();
    outmma_kernel<<<dim3(32, 8, 8), 256, OM_SMEM>>>(x, gamma, out);
}